// round 12
// baseline (speedup 1.0000x reference)
#include <cuda_runtime.h>
#include <cuda_bf16.h>
#include <math.h>
#include <stdint.h>

// Problem constants
#define Bb 16
#define Ss 128
#define Ee 512
#define Hh 1024
#define G4 4096
#define Vv 32000

// ---------------- static scratch (no allocations allowed) ----------------
__device__ float g_pre[2048 * 4096];         // precomputed input gates + bias [T*B, 4H]
__device__ float g_seq[2048 * 1024];         // layer output sequence [T*B, H]
__device__ __nv_bfloat16 g_ah[2048 * 1024];  // A operand hi
__device__ __nv_bfloat16 g_al[2048 * 1024];  // A operand lo
__device__ __nv_bfloat16 g_wh[32000 * 1024]; // W operand hi (reused per GEMM)
__device__ __nv_bfloat16 g_wl[32000 * 1024]; // W operand lo
__device__ float g_hA[16 * 1024];
__device__ float g_hB[16 * 1024];
__device__ float g_c[16 * 1024];
__device__ float g_h0f[16 * 1024];
__device__ float g_c0f[16 * 1024];
__device__ float g_h1f[16 * 1024];
__device__ float g_c1f[16 * 1024];
__device__ unsigned g_bar;

// ---------------- PTX helpers ----------------
__device__ __forceinline__ uint32_t smem_u32(const void* p) {
    uint32_t a;
    asm("{ .reg .u64 t; cvta.to.shared.u64 t, %1; cvt.u32.u64 %0, t; }" : "=r"(a) : "l"(p));
    return a;
}

__device__ __forceinline__ void cp16(uint32_t dst, const void* src, int sz) {
    asm volatile("cp.async.cg.shared.global [%0], [%1], 16, %2;"
                 :: "r"(dst), "l"(src), "r"(sz) : "memory");
}

#define LDSM4(r0, r1, r2, r3, addr) \
    asm volatile("ldmatrix.sync.aligned.m8n8.x4.shared.b16 {%0,%1,%2,%3}, [%4];" \
                 : "=r"(r0), "=r"(r1), "=r"(r2), "=r"(r3) : "r"(addr))

#define MMA16816(c, a0, a1, a2, a3, b0, b1) \
    asm volatile("mma.sync.aligned.m16n8k16.row.col.f32.bf16.bf16.f32 " \
                 "{%0,%1,%2,%3}, {%4,%5,%6,%7}, {%8,%9}, {%0,%1,%2,%3};" \
                 : "+f"((c)[0]), "+f"((c)[1]), "+f"((c)[2]), "+f"((c)[3]) \
                 : "r"(a0), "r"(a1), "r"(a2), "r"(a3), "r"(b0), "r"(b1))

// ---------------- tiny utility kernels ----------------
__global__ void zero_kernel(float* __restrict__ p, int n) {
    int i = blockIdx.x * blockDim.x + threadIdx.x;
    if (i < n) p[i] = 0.0f;
}

__global__ void zero_bar_kernel() { g_bar = 0u; }

__global__ void copy_kernel(float* __restrict__ dst, const float* __restrict__ src, int n) {
    int i = blockIdx.x * blockDim.x + threadIdx.x;
    if (i < n) dst[i] = src[i];
}

__global__ void zero_t0_kernel(float* __restrict__ out) {
    int i = blockIdx.x * blockDim.x + threadIdx.x;
    if (i < Bb * Vv) {
        int m = i / Vv;
        int n = i - m * Vv;
        out[(size_t)m * Ss * Vv + n] = 0.0f;
    }
}

// split fp32 -> bf16 hi + bf16 lo (vec4)
__global__ void split4_kernel(const float* __restrict__ in, __nv_bfloat16* __restrict__ hi,
                              __nv_bfloat16* __restrict__ lo, int n4) {
    int i = blockIdx.x * blockDim.x + threadIdx.x;
    if (i >= n4) return;
    float4 v = ((const float4*)in)[i];
    __nv_bfloat16 h0 = __float2bfloat16(v.x);
    __nv_bfloat16 h1 = __float2bfloat16(v.y);
    __nv_bfloat16 h2 = __float2bfloat16(v.z);
    __nv_bfloat16 h3 = __float2bfloat16(v.w);
    __nv_bfloat162* H = (__nv_bfloat162*)hi;
    __nv_bfloat162* L = (__nv_bfloat162*)lo;
    H[2 * i + 0] = __nv_bfloat162(h0, h1);
    H[2 * i + 1] = __nv_bfloat162(h2, h3);
    L[2 * i + 0] = __nv_bfloat162(__float2bfloat16(v.x - __bfloat162float(h0)),
                                  __float2bfloat16(v.y - __bfloat162float(h1)));
    L[2 * i + 1] = __nv_bfloat162(__float2bfloat16(v.z - __bfloat162float(h2)),
                                  __float2bfloat16(v.w - __bfloat162float(h3)));
}

// Embedding gather + bf16 split: out rows [(t*B+m), E]
__global__ void gather_split_kernel(const int* __restrict__ tok, const float* __restrict__ emb,
                                    __nv_bfloat16* __restrict__ hi, __nv_bfloat16* __restrict__ lo,
                                    int T) {
    int idx = blockIdx.x * blockDim.x + threadIdx.x;  // float2 index
    int total = T * Bb * (Ee / 2);
    if (idx >= total) return;
    int e2 = idx & (Ee / 2 - 1);
    int r = idx >> 8;
    int m = r & (Bb - 1);
    int t = r >> 4;
    int token = tok[m * Ss + t];
    float2 v = *(const float2*)(emb + (size_t)token * Ee + e2 * 2);
    __nv_bfloat16 h0 = __float2bfloat16(v.x);
    __nv_bfloat16 h1 = __float2bfloat16(v.y);
    ((__nv_bfloat162*)hi)[(size_t)r * (Ee / 2) + e2] = __nv_bfloat162(h0, h1);
    ((__nv_bfloat162*)lo)[(size_t)r * (Ee / 2) + e2] =
        __nv_bfloat162(__float2bfloat16(v.x - __bfloat162float(h0)),
                       __float2bfloat16(v.y - __bfloat162float(h1)));
}

// ---------------- mma.sync split-bf16 GEMM (8 warps, 4-stage pipeline) ----------------
#define RSB 80
#define TILE_BYTES (128 * RSB)        // 10240
#define STAGE_BYTES (4 * TILE_BYTES)  // 40960 (Ah, Al, Bh, Bl)
#define NSTAGE 4
#define GEMM_SMEM (NSTAGE * STAGE_BYTES)  // 163840

__device__ __forceinline__ void load_stage_mma(
    uint32_t base, const __nv_bfloat16* __restrict__ Ah, const __nv_bfloat16* __restrict__ Al,
    const __nv_bfloat16* __restrict__ Bh, const __nv_bfloat16* __restrict__ Bl,
    int m0, int n0, int M, int K, int kc, int tid) {
    int k0 = kc * 32;
#pragma unroll
    for (int i = 0; i < 2; i++) {
        int chunk = tid + (i << 8);   // 0..511
        int row = chunk >> 2;         // 0..127
        int c4 = chunk & 3;           // 16B chunk within 64B row
        uint32_t smoff = row * RSB + c4 * 16;
        int gk = k0 + c4 * 8;
        int gm = m0 + row;
        int oka = (gm < M);
        size_t aoff = (size_t)(oka ? gm : 0) * K + gk;
        cp16(base + smoff, Ah + aoff, oka ? 16 : 0);
        cp16(base + TILE_BYTES + smoff, Al + aoff, oka ? 16 : 0);
        size_t boff = (size_t)(n0 + row) * K + gk;
        cp16(base + 2 * TILE_BYTES + smoff, Bh + boff, 16);
        cp16(base + 3 * TILE_BYTES + smoff, Bl + boff, 16);
    }
}

__global__ __launch_bounds__(256) void gemm_mma_kernel(
    const __nv_bfloat16* __restrict__ Ah, const __nv_bfloat16* __restrict__ Al,
    const __nv_bfloat16* __restrict__ Bh, const __nv_bfloat16* __restrict__ Bl,
    const float* __restrict__ bias, float* __restrict__ C,
    int M, int N, int K, int mode) {
    extern __shared__ char smem[];
    uint32_t sb = smem_u32(smem);
    int tid = threadIdx.x;
    int lane = tid & 31;
    int warp = tid >> 5;
    int wm = (warp >> 2) * 64;
    int wn = (warp & 3) * 32;
    int m0 = blockIdx.y * 128;
    int n0 = blockIdx.x * 128;

    float acc[4][4][4];
#pragma unroll
    for (int i = 0; i < 4; i++)
#pragma unroll
        for (int j = 0; j < 4; j++)
#pragma unroll
            for (int q = 0; q < 4; q++) acc[i][j][q] = 0.0f;

    const int NC = K >> 5;

#pragma unroll
    for (int s = 0; s < NSTAGE - 1; s++) {
        load_stage_mma(sb + s * STAGE_BYTES, Ah, Al, Bh, Bl, m0, n0, M, K, s, tid);
        asm volatile("cp.async.commit_group;" ::: "memory");
    }

    uint32_t a_row = wm + (lane & 15);
    uint32_t a_kb = (lane >> 4) * 16;
    uint32_t b_row = wn + (lane & 7) + ((lane >> 4) << 3);
    uint32_t b_kb = ((lane >> 3) & 1) * 16;

    int slot = 0;
    int lslot = NSTAGE - 1;

    for (int kc = 0; kc < NC; kc++) {
        asm volatile("cp.async.wait_group %0;" :: "n"(NSTAGE - 2) : "memory");
        __syncthreads();
        if (kc + NSTAGE - 1 < NC) {
            load_stage_mma(sb + lslot * STAGE_BYTES, Ah, Al, Bh, Bl, m0, n0, M, K,
                           kc + NSTAGE - 1, tid);
        }
        asm volatile("cp.async.commit_group;" ::: "memory");

        uint32_t stage = sb + slot * STAGE_BYTES;
#pragma unroll
        for (int kk = 0; kk < 2; kk++) {
            uint32_t kbyte = kk * 32;
            uint32_t ah[4][4], al[4][4];
#pragma unroll
            for (int mi = 0; mi < 4; mi++) {
                uint32_t ad = stage + (a_row + mi * 16) * RSB + kbyte + a_kb;
                LDSM4(ah[mi][0], ah[mi][1], ah[mi][2], ah[mi][3], ad);
            }
#pragma unroll
            for (int mi = 0; mi < 4; mi++) {
                uint32_t ad = stage + TILE_BYTES + (a_row + mi * 16) * RSB + kbyte + a_kb;
                LDSM4(al[mi][0], al[mi][1], al[mi][2], al[mi][3], ad);
            }
#pragma unroll
            for (int ni = 0; ni < 2; ni++) {
                uint32_t b0, b1, b2, b3;
                uint32_t bd = stage + 2 * TILE_BYTES + (b_row + ni * 16) * RSB + kbyte + b_kb;
                LDSM4(b0, b1, b2, b3, bd);  // Bh n16
#pragma unroll
                for (int mi = 0; mi < 4; mi++) {
                    MMA16816(acc[mi][ni * 2], ah[mi][0], ah[mi][1], ah[mi][2], ah[mi][3], b0, b1);
                    MMA16816(acc[mi][ni * 2 + 1], ah[mi][0], ah[mi][1], ah[mi][2], ah[mi][3], b2, b3);
                }
#pragma unroll
                for (int mi = 0; mi < 4; mi++) {
                    MMA16816(acc[mi][ni * 2], al[mi][0], al[mi][1], al[mi][2], al[mi][3], b0, b1);
                    MMA16816(acc[mi][ni * 2 + 1], al[mi][0], al[mi][1], al[mi][2], al[mi][3], b2, b3);
                }
                uint32_t ld = stage + 3 * TILE_BYTES + (b_row + ni * 16) * RSB + kbyte + b_kb;
                LDSM4(b0, b1, b2, b3, ld);  // Bl n16
#pragma unroll
                for (int mi = 0; mi < 4; mi++) {
                    MMA16816(acc[mi][ni * 2], ah[mi][0], ah[mi][1], ah[mi][2], ah[mi][3], b0, b1);
                    MMA16816(acc[mi][ni * 2 + 1], ah[mi][0], ah[mi][1], ah[mi][2], ah[mi][3], b2, b3);
                }
            }
        }
        slot = (slot + 1 == NSTAGE) ? 0 : slot + 1;
        lslot = (lslot + 1 == NSTAGE) ? 0 : lslot + 1;
    }

    int rbase = m0 + wm + (lane >> 2);
    int cbase = n0 + wn + 2 * (lane & 3);
#pragma unroll
    for (int mi = 0; mi < 4; mi++) {
#pragma unroll
        for (int half = 0; half < 2; half++) {
            int m = rbase + mi * 16 + half * 8;
            if (m >= M) continue;
            int orow = mode ? ((m & (Bb - 1)) * Ss + (m >> 4) + 1) : m;
            float* crow = C + (size_t)orow * N;
#pragma unroll
            for (int nj = 0; nj < 4; nj++) {
                int n = cbase + nj * 8;
                float2 v;
                v.x = acc[mi][nj][half * 2 + 0] + bias[n];
                v.y = acc[mi][nj][half * 2 + 1] + bias[n + 1];
                *(float2*)(crow + n) = v;
            }
        }
    }
}

// ---------------- persistent LSTM layer kernel (broadcast-h, f32x2 FFMA) ----------------
// 128 CTAs x 256 threads. warp = k-chunk (8 x 128), lane = gate-row (32 rows =
// 4 gates x 8 units). Each thread accumulates all 16 batches in packed f32x2
// registers; h smem reads are warp-wide broadcast ld.shared.v2.b64.
#define WSS 1028
#define HSS 1028
#define LSTM_SMEM ((32 * WSS + 16 * HSS + 128 * 33 + 128) * 4)

__global__ __launch_bounds__(256) void lstm_layer_kernel(
    const float* __restrict__ pre, const float* __restrict__ Whh,
    const float* __restrict__ h_init, const float* __restrict__ c_init,
    float* __restrict__ hb0, float* __restrict__ hb1,
    float* __restrict__ y, float* __restrict__ c_fin, int T) {
    extern __shared__ float sm[];
    float* ws = sm;                         // 32 x WSS
    float* hs = sm + 32 * WSS;              // 16 x HSS
    float* red = sm + 32 * WSS + 16 * HSS;  // 128 x 33: red[(m*8+w)*33 + lane]
    float* cs = red + 128 * 33;             // 128

    int tid = threadIdx.x;
    int lane = tid & 31;
    int warp = tid >> 5;
    int j0 = blockIdx.x * 8;

    // Load Whh slice once: smem row r = g*8+jj -> global row g*H + j0 + jj
    for (int idx = tid; idx < 32 * 256; idx += 256) {
        int r = idx >> 8;
        int c4 = idx & 255;
        int g = r >> 3, jj = r & 7;
        float4 v = *(const float4*)(Whh + (size_t)(g * Hh + j0 + jj) * Hh + c4 * 4);
        *(float4*)(ws + r * WSS + c4 * 4) = v;
    }
    if (tid < 128) {
        int m = tid & 15, jr = tid >> 4;
        cs[tid] = c_init[m * Hh + j0 + jr];
    }
    __syncthreads();

    uint32_t waddr = smem_u32(ws) + (uint32_t)(lane * WSS + warp * 128) * 4u;
    uint32_t haddr0 = smem_u32(hs) + (uint32_t)(warp * 128) * 4u;

    for (int s = 0; s < T; s++) {
        // stage h[B,H] into smem (bypass L1: other SMs wrote it last step)
        const float* hsrc = (s == 0) ? h_init : ((s & 1) ? hb1 : hb0);
        for (int idx = tid; idx < 16 * 256; idx += 256) {
            int m = idx >> 8, c4 = idx & 255;
            float4 v = __ldcg((const float4*)(hsrc + (size_t)m * Hh + c4 * 4));
            *(float4*)(hs + m * HSS + c4 * 4) = v;
        }
        __syncthreads();

        unsigned long long acc2[16];
#pragma unroll
        for (int m = 0; m < 16; m++) acc2[m] = 0ull;  // {0.f, 0.f}

#pragma unroll 4
        for (int kk = 0; kk < 128; kk += 4) {
            unsigned long long w01, w23;
            asm("ld.shared.v2.b64 {%0, %1}, [%2];"
                : "=l"(w01), "=l"(w23) : "r"(waddr + (uint32_t)kk * 4u));
#pragma unroll
            for (int m = 0; m < 16; m++) {
                unsigned long long h01, h23;
                asm("ld.shared.v2.b64 {%0, %1}, [%2];"
                    : "=l"(h01), "=l"(h23)
                    : "r"(haddr0 + (uint32_t)(m * HSS + kk) * 4u));
                asm("fma.rn.f32x2 %0, %1, %2, %0;" : "+l"(acc2[m]) : "l"(w01), "l"(h01));
                asm("fma.rn.f32x2 %0, %1, %2, %0;" : "+l"(acc2[m]) : "l"(w23), "l"(h23));
            }
        }
        // partials: red[(m*8+warp)*33 + lane] — conflict-free stores
#pragma unroll
        for (int m = 0; m < 16; m++) {
            uint32_t lo, hi;
            asm("mov.b64 {%0, %1}, %2;" : "=r"(lo), "=r"(hi) : "l"(acc2[m]));
            red[(m * 8 + warp) * 33 + lane] = __uint_as_float(lo) + __uint_as_float(hi);
        }
        __syncthreads();

        if (tid < 128) {
            int m = tid & 15, jr = tid >> 4;
            float gate[4];
#pragma unroll
            for (int g = 0; g < 4; g++) {
                int r = g * 8 + jr;
                float sum = 0.0f;
#pragma unroll
                for (int w = 0; w < 8; w++) sum += red[(m * 8 + w) * 33 + r];
                gate[g] = sum;
            }
            const float* pm = pre + (size_t)(s * Bb + m) * G4 + j0 + jr;
            float pi = pm[0] + gate[0];
            float pf = pm[Hh] + gate[1];
            float pg = pm[2 * Hh] + gate[2];
            float po = pm[3 * Hh] + gate[3];
            float iv = 1.0f / (1.0f + expf(-pi));
            float fv = 1.0f / (1.0f + expf(-pf));
            float gv = tanhf(pg);
            float ov = 1.0f / (1.0f + expf(-po));
            float cn = fv * cs[tid] + iv * gv;
            float hn = ov * tanhf(cn);
            cs[tid] = cn;
            float* hdst = ((s + 1) & 1) ? hb1 : hb0;
            hdst[m * Hh + j0 + jr] = hn;
            if (y) y[(size_t)(s * Bb + m) * Hh + j0 + jr] = hn;
        }
        __threadfence();
        __syncthreads();
        if (tid == 0) {
            atomicAdd(&g_bar, 1u);
            unsigned target = (unsigned)(s + 1) * 128u;
            while (*(volatile unsigned*)&g_bar < target) {}
            __threadfence();
        }
        __syncthreads();
    }

    if (c_fin && tid < 128) {
        int m = tid & 15, jr = tid >> 4;
        c_fin[m * Hh + j0 + jr] = cs[tid];
    }
}

// ---------------- host orchestration ----------------
static inline void split_w(const float* w, __nv_bfloat16* hi, __nv_bfloat16* lo, int n) {
    int n4 = n / 4;
    split4_kernel<<<(n4 + 255) / 256, 256>>>(w, hi, lo, n4);
}

static inline void gemm_tc(const __nv_bfloat16* Ah, const __nv_bfloat16* Al,
                           const __nv_bfloat16* Bh, const __nv_bfloat16* Bl,
                           const float* bias, float* C, int M, int N, int K, int mode) {
    dim3 grid(N / 128, (M + 127) / 128);
    gemm_mma_kernel<<<grid, 256, GEMM_SMEM>>>(Ah, Al, Bh, Bl, bias, C, M, N, K, mode);
}

static inline void run_lstm_layer(const float* pre, const float* Whh, const float* h_init,
                                  const float* c_init, float* hb0, float* hb1, float* y,
                                  float* c_fin, int T) {
    zero_bar_kernel<<<1, 1>>>();
    lstm_layer_kernel<<<128, 256, LSTM_SMEM>>>(pre, Whh, h_init, c_init, hb0, hb1, y,
                                               c_fin, T);
}

extern "C" void kernel_launch(void* const* d_in, const int* in_sizes, int n_in,
                              void* d_out, int out_size) {
    const int* src = (const int*)d_in[0];
    const int* trg = (const int*)d_in[1];
    const float* enc_emb = (const float*)d_in[2];
    const float* dec_emb = (const float*)d_in[3];
    const float* enc_Wih0 = (const float*)d_in[4];
    const float* enc_Whh0 = (const float*)d_in[5];
    const float* enc_b0 = (const float*)d_in[6];
    const float* enc_Wih1 = (const float*)d_in[7];
    const float* enc_Whh1 = (const float*)d_in[8];
    const float* enc_b1 = (const float*)d_in[9];
    const float* dec_Wih0 = (const float*)d_in[10];
    const float* dec_Whh0 = (const float*)d_in[11];
    const float* dec_b0 = (const float*)d_in[12];
    const float* dec_Wih1 = (const float*)d_in[13];
    const float* dec_Whh1 = (const float*)d_in[14];
    const float* dec_b1 = (const float*)d_in[15];
    const float* fc_W = (const float*)d_in[16];
    const float* fc_b = (const float*)d_in[17];
    float* out = (float*)d_out;

    cudaFuncSetAttribute(gemm_mma_kernel, cudaFuncAttributeMaxDynamicSharedMemorySize,
                         GEMM_SMEM);
    cudaFuncSetAttribute(lstm_layer_kernel, cudaFuncAttributeMaxDynamicSharedMemorySize,
                         LSTM_SMEM);

    float *pre, *seq, *hA, *hB, *cb, *h0f, *c0f, *h1f, *c1f;
    __nv_bfloat16 *ah, *al, *wh, *wl;
    cudaGetSymbolAddress((void**)&pre, g_pre);
    cudaGetSymbolAddress((void**)&seq, g_seq);
    cudaGetSymbolAddress((void**)&ah, g_ah);
    cudaGetSymbolAddress((void**)&al, g_al);
    cudaGetSymbolAddress((void**)&wh, g_wh);
    cudaGetSymbolAddress((void**)&wl, g_wl);
    cudaGetSymbolAddress((void**)&hA, g_hA);
    cudaGetSymbolAddress((void**)&hB, g_hB);
    cudaGetSymbolAddress((void**)&cb, g_c);
    cudaGetSymbolAddress((void**)&h0f, g_h0f);
    cudaGetSymbolAddress((void**)&c0f, g_c0f);
    cudaGetSymbolAddress((void**)&h1f, g_h1f);
    cudaGetSymbolAddress((void**)&c1f, g_c1f);

    const int NST = Bb * Hh;

    // ================= ENCODER layer 0 =================
    {
        int total = Ss * Bb * (Ee / 2);
        gather_split_kernel<<<(total + 255) / 256, 256>>>(src, enc_emb, ah, al, Ss);
    }
    split_w(enc_Wih0, wh, wl, G4 * Ee);
    gemm_tc(ah, al, wh, wl, enc_b0, pre, Bb * Ss, G4, Ee, 0);
    zero_kernel<<<(NST + 255) / 256, 256>>>(hA, NST);
    zero_kernel<<<(NST + 255) / 256, 256>>>(cb, NST);
    run_lstm_layer(pre, enc_Whh0, hA, cb, hA, hB, seq, c0f, Ss);
    copy_kernel<<<(NST + 255) / 256, 256>>>(h0f, hA, NST);

    // ================= ENCODER layer 1 (only final state needed) =================
    split_w(seq, ah, al, Bb * Ss * Hh);
    split_w(enc_Wih1, wh, wl, G4 * Hh);
    gemm_tc(ah, al, wh, wl, enc_b1, pre, Bb * Ss, G4, Hh, 0);
    zero_kernel<<<(NST + 255) / 256, 256>>>(hA, NST);
    zero_kernel<<<(NST + 255) / 256, 256>>>(cb, NST);
    run_lstm_layer(pre, enc_Whh1, hA, cb, hA, hB, (float*)0, c1f, Ss);
    copy_kernel<<<(NST + 255) / 256, 256>>>(h1f, hA, NST);

    // ================= DECODER layer 0 (T = 127) =================
    const int Td = Ss - 1;
    {
        int total = Td * Bb * (Ee / 2);
        gather_split_kernel<<<(total + 255) / 256, 256>>>(trg, dec_emb, ah, al, Td);
    }
    split_w(dec_Wih0, wh, wl, G4 * Ee);
    gemm_tc(ah, al, wh, wl, dec_b0, pre, Bb * Td, G4, Ee, 0);
    run_lstm_layer(pre, dec_Whh0, h0f, c0f, hA, hB, seq, (float*)0, Td);

    // ================= DECODER layer 1 =================
    split_w(seq, ah, al, Bb * Td * Hh);
    split_w(dec_Wih1, wh, wl, G4 * Hh);
    gemm_tc(ah, al, wh, wl, dec_b1, pre, Bb * Td, G4, Hh, 0);
    run_lstm_layer(pre, dec_Whh1, h1f, c1f, hA, hB, seq, (float*)0, Td);

    // ================= Classifier =================
    split_w(seq, ah, al, Bb * Td * Hh);
    split_w(fc_W, wh, wl, Vv * Hh);
    zero_t0_kernel<<<(Bb * Vv + 255) / 256, 256>>>(out);
    gemm_tc(ah, al, wh, wl, fc_b, out, Bb * Td, Vv, Hh, 1);
}

// round 13
// speedup vs baseline: 1.0081x; 1.0081x over previous
#include <cuda_runtime.h>
#include <cuda_bf16.h>
#include <math.h>
#include <stdint.h>

// Problem constants
#define Bb 16
#define Ss 128
#define Ee 512
#define Hh 1024
#define G4 4096
#define Vv 32000

// ---------------- static scratch (no allocations allowed) ----------------
__device__ float g_pre[2048 * 4096];         // precomputed input gates + bias [T*B, 4H]
__device__ float g_seq[2048 * 1024];         // layer output sequence [T*B, H]
__device__ __nv_bfloat16 g_ah[2048 * 1024];  // A operand hi
__device__ __nv_bfloat16 g_al[2048 * 1024];  // A operand lo
__device__ __nv_bfloat16 g_wh[32000 * 1024]; // W operand hi (reused per GEMM)
__device__ __nv_bfloat16 g_wl[32000 * 1024]; // W operand lo
__device__ float g_hA[16 * 1024];
__device__ float g_hB[16 * 1024];
__device__ float g_c[16 * 1024];
__device__ float g_h0f[16 * 1024];
__device__ float g_c0f[16 * 1024];
__device__ float g_h1f[16 * 1024];
__device__ float g_c1f[16 * 1024];
__device__ unsigned g_bar;

// ---------------- PTX helpers ----------------
__device__ __forceinline__ uint32_t smem_u32(const void* p) {
    uint32_t a;
    asm("{ .reg .u64 t; cvta.to.shared.u64 t, %1; cvt.u32.u64 %0, t; }" : "=r"(a) : "l"(p));
    return a;
}

__device__ __forceinline__ void cp16(uint32_t dst, const void* src, int sz) {
    asm volatile("cp.async.cg.shared.global [%0], [%1], 16, %2;"
                 :: "r"(dst), "l"(src), "r"(sz) : "memory");
}

#define LDSM4(r0, r1, r2, r3, addr) \
    asm volatile("ldmatrix.sync.aligned.m8n8.x4.shared.b16 {%0,%1,%2,%3}, [%4];" \
                 : "=r"(r0), "=r"(r1), "=r"(r2), "=r"(r3) : "r"(addr))

#define MMA16816(c, a0, a1, a2, a3, b0, b1) \
    asm volatile("mma.sync.aligned.m16n8k16.row.col.f32.bf16.bf16.f32 " \
                 "{%0,%1,%2,%3}, {%4,%5,%6,%7}, {%8,%9}, {%0,%1,%2,%3};" \
                 : "+f"((c)[0]), "+f"((c)[1]), "+f"((c)[2]), "+f"((c)[3]) \
                 : "r"(a0), "r"(a1), "r"(a2), "r"(a3), "r"(b0), "r"(b1))

// ---------------- tiny utility kernels ----------------
__global__ void zero_bar_kernel() { g_bar = 0u; }

__global__ void zero2_kernel(float* __restrict__ a, float* __restrict__ b, int n) {
    int i = blockIdx.x * blockDim.x + threadIdx.x;
    if (i < n) { a[i] = 0.0f; b[i] = 0.0f; }
}

__global__ void copy_kernel(float* __restrict__ dst, const float* __restrict__ src, int n) {
    int i = blockIdx.x * blockDim.x + threadIdx.x;
    if (i < n) dst[i] = src[i];
}

__global__ void zero_t0_kernel(float* __restrict__ out) {
    int i = blockIdx.x * blockDim.x + threadIdx.x;
    if (i < Bb * Vv) {
        int m = i / Vv;
        int n = i - m * Vv;
        out[(size_t)m * Ss * Vv + n] = 0.0f;
    }
}

// split fp32 -> bf16 hi + bf16 lo (vec4)
__global__ void split4_kernel(const float* __restrict__ in, __nv_bfloat16* __restrict__ hi,
                              __nv_bfloat16* __restrict__ lo, int n4) {
    int i = blockIdx.x * blockDim.x + threadIdx.x;
    if (i >= n4) return;
    float4 v = ((const float4*)in)[i];
    __nv_bfloat16 h0 = __float2bfloat16(v.x);
    __nv_bfloat16 h1 = __float2bfloat16(v.y);
    __nv_bfloat16 h2 = __float2bfloat16(v.z);
    __nv_bfloat16 h3 = __float2bfloat16(v.w);
    __nv_bfloat162* H = (__nv_bfloat162*)hi;
    __nv_bfloat162* L = (__nv_bfloat162*)lo;
    H[2 * i + 0] = __nv_bfloat162(h0, h1);
    H[2 * i + 1] = __nv_bfloat162(h2, h3);
    L[2 * i + 0] = __nv_bfloat162(__float2bfloat16(v.x - __bfloat162float(h0)),
                                  __float2bfloat16(v.y - __bfloat162float(h1)));
    L[2 * i + 1] = __nv_bfloat162(__float2bfloat16(v.z - __bfloat162float(h2)),
                                  __float2bfloat16(v.w - __bfloat162float(h3)));
}

// Embedding gather + bf16 split: out rows [(t*B+m), E]
__global__ void gather_split_kernel(const int* __restrict__ tok, const float* __restrict__ emb,
                                    __nv_bfloat16* __restrict__ hi, __nv_bfloat16* __restrict__ lo,
                                    int T) {
    int idx = blockIdx.x * blockDim.x + threadIdx.x;  // float2 index
    int total = T * Bb * (Ee / 2);
    if (idx >= total) return;
    int e2 = idx & (Ee / 2 - 1);
    int r = idx >> 8;
    int m = r & (Bb - 1);
    int t = r >> 4;
    int token = tok[m * Ss + t];
    float2 v = *(const float2*)(emb + (size_t)token * Ee + e2 * 2);
    __nv_bfloat16 h0 = __float2bfloat16(v.x);
    __nv_bfloat16 h1 = __float2bfloat16(v.y);
    ((__nv_bfloat162*)hi)[(size_t)r * (Ee / 2) + e2] = __nv_bfloat162(h0, h1);
    ((__nv_bfloat162*)lo)[(size_t)r * (Ee / 2) + e2] =
        __nv_bfloat162(__float2bfloat16(v.x - __bfloat162float(h0)),
                       __float2bfloat16(v.y - __bfloat162float(h1)));
}

// ---------------- mma.sync split-bf16 GEMM (8 warps, 3-stage pipeline) ----------------
#define RSB 80
#define TILE_BYTES (128 * RSB)        // 10240
#define STAGE_BYTES (4 * TILE_BYTES)  // 40960 (Ah, Al, Bh, Bl)
#define NSTAGE 3
#define GEMM_SMEM (NSTAGE * STAGE_BYTES)  // 122880

__device__ __forceinline__ void load_stage_mma(
    uint32_t base, const __nv_bfloat16* __restrict__ Ah, const __nv_bfloat16* __restrict__ Al,
    const __nv_bfloat16* __restrict__ Bh, const __nv_bfloat16* __restrict__ Bl,
    int m0, int n0, int M, int K, int kc, int tid) {
    int k0 = kc * 32;
#pragma unroll
    for (int i = 0; i < 2; i++) {
        int chunk = tid + (i << 8);   // 0..511
        int row = chunk >> 2;         // 0..127
        int c4 = chunk & 3;           // 16B chunk within 64B row
        uint32_t smoff = row * RSB + c4 * 16;
        int gk = k0 + c4 * 8;
        int gm = m0 + row;
        int oka = (gm < M);
        size_t aoff = (size_t)(oka ? gm : 0) * K + gk;
        cp16(base + smoff, Ah + aoff, oka ? 16 : 0);
        cp16(base + TILE_BYTES + smoff, Al + aoff, oka ? 16 : 0);
        size_t boff = (size_t)(n0 + row) * K + gk;
        cp16(base + 2 * TILE_BYTES + smoff, Bh + boff, 16);
        cp16(base + 3 * TILE_BYTES + smoff, Bl + boff, 16);
    }
}

__global__ __launch_bounds__(256) void gemm_mma_kernel(
    const __nv_bfloat16* __restrict__ Ah, const __nv_bfloat16* __restrict__ Al,
    const __nv_bfloat16* __restrict__ Bh, const __nv_bfloat16* __restrict__ Bl,
    const float* __restrict__ bias, float* __restrict__ C,
    int M, int N, int K, int mode) {
    extern __shared__ char smem[];
    uint32_t sb = smem_u32(smem);
    int tid = threadIdx.x;
    int lane = tid & 31;
    int warp = tid >> 5;
    int wm = (warp >> 2) * 64;
    int wn = (warp & 3) * 32;
    int m0 = blockIdx.y * 128;
    int n0 = blockIdx.x * 128;

    float acc[4][4][4];
#pragma unroll
    for (int i = 0; i < 4; i++)
#pragma unroll
        for (int j = 0; j < 4; j++)
#pragma unroll
            for (int q = 0; q < 4; q++) acc[i][j][q] = 0.0f;

    const int NC = K >> 5;

#pragma unroll
    for (int s = 0; s < NSTAGE - 1; s++) {
        load_stage_mma(sb + s * STAGE_BYTES, Ah, Al, Bh, Bl, m0, n0, M, K, s, tid);
        asm volatile("cp.async.commit_group;" ::: "memory");
    }

    uint32_t a_row = wm + (lane & 15);
    uint32_t a_kb = (lane >> 4) * 16;
    uint32_t b_row = wn + (lane & 7) + ((lane >> 4) << 3);
    uint32_t b_kb = ((lane >> 3) & 1) * 16;

    int slot = 0;
    int lslot = NSTAGE - 1;

    for (int kc = 0; kc < NC; kc++) {
        asm volatile("cp.async.wait_group %0;" :: "n"(NSTAGE - 2) : "memory");
        __syncthreads();
        if (kc + NSTAGE - 1 < NC) {
            load_stage_mma(sb + lslot * STAGE_BYTES, Ah, Al, Bh, Bl, m0, n0, M, K,
                           kc + NSTAGE - 1, tid);
        }
        asm volatile("cp.async.commit_group;" ::: "memory");

        uint32_t stage = sb + slot * STAGE_BYTES;
#pragma unroll
        for (int kk = 0; kk < 2; kk++) {
            uint32_t kbyte = kk * 32;
            uint32_t ah[4][4], al[4][4];
#pragma unroll
            for (int mi = 0; mi < 4; mi++) {
                uint32_t ad = stage + (a_row + mi * 16) * RSB + kbyte + a_kb;
                LDSM4(ah[mi][0], ah[mi][1], ah[mi][2], ah[mi][3], ad);
            }
#pragma unroll
            for (int mi = 0; mi < 4; mi++) {
                uint32_t ad = stage + TILE_BYTES + (a_row + mi * 16) * RSB + kbyte + a_kb;
                LDSM4(al[mi][0], al[mi][1], al[mi][2], al[mi][3], ad);
            }
#pragma unroll
            for (int ni = 0; ni < 2; ni++) {
                uint32_t b0, b1, b2, b3;
                uint32_t bd = stage + 2 * TILE_BYTES + (b_row + ni * 16) * RSB + kbyte + b_kb;
                LDSM4(b0, b1, b2, b3, bd);  // Bh n16
#pragma unroll
                for (int mi = 0; mi < 4; mi++) {
                    MMA16816(acc[mi][ni * 2], ah[mi][0], ah[mi][1], ah[mi][2], ah[mi][3], b0, b1);
                    MMA16816(acc[mi][ni * 2 + 1], ah[mi][0], ah[mi][1], ah[mi][2], ah[mi][3], b2, b3);
                }
#pragma unroll
                for (int mi = 0; mi < 4; mi++) {
                    MMA16816(acc[mi][ni * 2], al[mi][0], al[mi][1], al[mi][2], al[mi][3], b0, b1);
                    MMA16816(acc[mi][ni * 2 + 1], al[mi][0], al[mi][1], al[mi][2], al[mi][3], b2, b3);
                }
                uint32_t ld = stage + 3 * TILE_BYTES + (b_row + ni * 16) * RSB + kbyte + b_kb;
                LDSM4(b0, b1, b2, b3, ld);  // Bl n16
#pragma unroll
                for (int mi = 0; mi < 4; mi++) {
                    MMA16816(acc[mi][ni * 2], ah[mi][0], ah[mi][1], ah[mi][2], ah[mi][3], b0, b1);
                    MMA16816(acc[mi][ni * 2 + 1], ah[mi][0], ah[mi][1], ah[mi][2], ah[mi][3], b2, b3);
                }
            }
        }
        slot = (slot + 1 == NSTAGE) ? 0 : slot + 1;
        lslot = (lslot + 1 == NSTAGE) ? 0 : lslot + 1;
    }

    int rbase = m0 + wm + (lane >> 2);
    int cbase = n0 + wn + 2 * (lane & 3);
#pragma unroll
    for (int mi = 0; mi < 4; mi++) {
#pragma unroll
        for (int half = 0; half < 2; half++) {
            int m = rbase + mi * 16 + half * 8;
            if (m >= M) continue;
            int orow = mode ? ((m & (Bb - 1)) * Ss + (m >> 4) + 1) : m;
            float* crow = C + (size_t)orow * N;
#pragma unroll
            for (int nj = 0; nj < 4; nj++) {
                int n = cbase + nj * 8;
                float2 v;
                v.x = acc[mi][nj][half * 2 + 0] + bias[n];
                v.y = acc[mi][nj][half * 2 + 1] + bias[n + 1];
                *(float2*)(crow + n) = v;
            }
        }
    }
}

// ---------------- persistent LSTM layer kernel (broadcast-h layout) ----------------
// 128 CTAs x 256 threads. warp = k-chunk (8 x 128), lane = gate-row (32 rows =
// 4 gates x 8 units). Each thread accumulates all 16 batches in registers; h
// smem reads are warp-wide broadcasts. Grid barrier counter is monotonic across
// layers (bar_base). pre gate values prefetched at step start (off critical path).
#define WSS 1028
#define HSS 1028
#define LSTM_SMEM ((32 * WSS + 16 * HSS + 128 * 33 + 128) * 4)

__global__ __launch_bounds__(256) void lstm_layer_kernel(
    const float* __restrict__ pre, const float* __restrict__ Whh,
    const float* __restrict__ h_init, const float* __restrict__ c_init,
    float* __restrict__ hb0, float* __restrict__ hb1,
    float* __restrict__ y, float* __restrict__ c_fin, int T, int bar_base) {
    extern __shared__ float sm[];
    float* ws = sm;                         // 32 x WSS
    float* hs = sm + 32 * WSS;              // 16 x HSS
    float* red = sm + 32 * WSS + 16 * HSS;  // 128 x 33: red[(m*8+w)*33 + lane]
    float* cs = red + 128 * 33;             // 128

    int tid = threadIdx.x;
    int lane = tid & 31;
    int warp = tid >> 5;
    int j0 = blockIdx.x * 8;

    // Load Whh slice once: smem row r = g*8+jj -> global row g*H + j0 + jj
    for (int idx = tid; idx < 32 * 256; idx += 256) {
        int r = idx >> 8;
        int c4 = idx & 255;
        int g = r >> 3, jj = r & 7;
        float4 v = *(const float4*)(Whh + (size_t)(g * Hh + j0 + jj) * Hh + c4 * 4);
        *(float4*)(ws + r * WSS + c4 * 4) = v;
    }
    if (tid < 128) {
        int m = tid & 15, jr = tid >> 4;
        cs[tid] = c_init[m * Hh + j0 + jr];
    }
    __syncthreads();

    const float* wrow = ws + lane * WSS + warp * 128;  // this thread's 128-k w chunk
    const float* hbase = hs + warp * 128;

    for (int s = 0; s < T; s++) {
        // prefetch this step's pre gate values (consumed after the reduction)
        float p0 = 0.f, p1 = 0.f, p2 = 0.f, p3 = 0.f;
        if (tid < 128) {
            int m = tid & 15, jr = tid >> 4;
            const float* pm = pre + (size_t)(s * Bb + m) * G4 + j0 + jr;
            p0 = __ldcg(pm);
            p1 = __ldcg(pm + Hh);
            p2 = __ldcg(pm + 2 * Hh);
            p3 = __ldcg(pm + 3 * Hh);
        }

        // stage h[B,H] into smem (bypass L1: other SMs wrote it last step)
        const float* hsrc = (s == 0) ? h_init : ((s & 1) ? hb1 : hb0);
        for (int idx = tid; idx < 16 * 256; idx += 256) {
            int m = idx >> 8, c4 = idx & 255;
            float4 v = __ldcg((const float4*)(hsrc + (size_t)m * Hh + c4 * 4));
            *(float4*)(hs + m * HSS + c4 * 4) = v;
        }
        __syncthreads();

        float acc[16];
#pragma unroll
        for (int m = 0; m < 16; m++) acc[m] = 0.0f;

#pragma unroll 4
        for (int kk = 0; kk < 128; kk += 4) {
            float4 wv = *(const float4*)(wrow + kk);
#pragma unroll
            for (int m = 0; m < 16; m++) {
                float4 hv = *(const float4*)(hbase + m * HSS + kk);  // broadcast
                acc[m] = fmaf(wv.x, hv.x, acc[m]);
                acc[m] = fmaf(wv.y, hv.y, acc[m]);
                acc[m] = fmaf(wv.z, hv.z, acc[m]);
                acc[m] = fmaf(wv.w, hv.w, acc[m]);
            }
        }
        // partials: red[(m*8+warp)*33 + lane] — conflict-free stores
#pragma unroll
        for (int m = 0; m < 16; m++) red[(m * 8 + warp) * 33 + lane] = acc[m];
        __syncthreads();

        if (tid < 128) {
            int m = tid & 15, jr = tid >> 4;
            float gate[4];
#pragma unroll
            for (int g = 0; g < 4; g++) {
                int r = g * 8 + jr;
                float sum = 0.0f;
#pragma unroll
                for (int w = 0; w < 8; w++) sum += red[(m * 8 + w) * 33 + r];
                gate[g] = sum;
            }
            float pi = p0 + gate[0];
            float pf = p1 + gate[1];
            float pg = p2 + gate[2];
            float po = p3 + gate[3];
            float iv = 1.0f / (1.0f + expf(-pi));
            float fv = 1.0f / (1.0f + expf(-pf));
            float gv = tanhf(pg);
            float ov = 1.0f / (1.0f + expf(-po));
            float cn = fv * cs[tid] + iv * gv;
            float hn = ov * tanhf(cn);
            cs[tid] = cn;
            float* hdst = ((s + 1) & 1) ? hb1 : hb0;
            hdst[m * Hh + j0 + jr] = hn;
            if (y) y[(size_t)(s * Bb + m) * Hh + j0 + jr] = hn;
        }
        __threadfence();
        __syncthreads();
        if (tid == 0) {
            atomicAdd(&g_bar, 1u);
            unsigned target = (unsigned)bar_base + (unsigned)(s + 1) * 128u;
            while (*(volatile unsigned*)&g_bar < target) {}
            __threadfence();
        }
        __syncthreads();
    }

    if (c_fin && tid < 128) {
        int m = tid & 15, jr = tid >> 4;
        c_fin[m * Hh + j0 + jr] = cs[tid];
    }
}

// ---------------- host orchestration ----------------
static inline void split_w(const float* w, __nv_bfloat16* hi, __nv_bfloat16* lo, int n) {
    int n4 = n / 4;
    split4_kernel<<<(n4 + 255) / 256, 256>>>(w, hi, lo, n4);
}

static inline void gemm_tc(const __nv_bfloat16* Ah, const __nv_bfloat16* Al,
                           const __nv_bfloat16* Bh, const __nv_bfloat16* Bl,
                           const float* bias, float* C, int M, int N, int K, int mode) {
    dim3 grid(N / 128, (M + 127) / 128);
    gemm_mma_kernel<<<grid, 256, GEMM_SMEM>>>(Ah, Al, Bh, Bl, bias, C, M, N, K, mode);
}

static inline void run_lstm_layer(const float* pre, const float* Whh, const float* h_init,
                                  const float* c_init, float* hb0, float* hb1, float* y,
                                  float* c_fin, int T, int bar_base) {
    lstm_layer_kernel<<<128, 256, LSTM_SMEM>>>(pre, Whh, h_init, c_init, hb0, hb1, y,
                                               c_fin, T, bar_base);
}

extern "C" void kernel_launch(void* const* d_in, const int* in_sizes, int n_in,
                              void* d_out, int out_size) {
    const int* src = (const int*)d_in[0];
    const int* trg = (const int*)d_in[1];
    const float* enc_emb = (const float*)d_in[2];
    const float* dec_emb = (const float*)d_in[3];
    const float* enc_Wih0 = (const float*)d_in[4];
    const float* enc_Whh0 = (const float*)d_in[5];
    const float* enc_b0 = (const float*)d_in[6];
    const float* enc_Wih1 = (const float*)d_in[7];
    const float* enc_Whh1 = (const float*)d_in[8];
    const float* enc_b1 = (const float*)d_in[9];
    const float* dec_Wih0 = (const float*)d_in[10];
    const float* dec_Whh0 = (const float*)d_in[11];
    const float* dec_b0 = (const float*)d_in[12];
    const float* dec_Wih1 = (const float*)d_in[13];
    const float* dec_Whh1 = (const float*)d_in[14];
    const float* dec_b1 = (const float*)d_in[15];
    const float* fc_W = (const float*)d_in[16];
    const float* fc_b = (const float*)d_in[17];
    float* out = (float*)d_out;

    cudaFuncSetAttribute(gemm_mma_kernel, cudaFuncAttributeMaxDynamicSharedMemorySize,
                         GEMM_SMEM);
    cudaFuncSetAttribute(lstm_layer_kernel, cudaFuncAttributeMaxDynamicSharedMemorySize,
                         LSTM_SMEM);

    float *pre, *seq, *hA, *hB, *cb, *h0f, *c0f, *h1f, *c1f;
    __nv_bfloat16 *ah, *al, *wh, *wl;
    cudaGetSymbolAddress((void**)&pre, g_pre);
    cudaGetSymbolAddress((void**)&seq, g_seq);
    cudaGetSymbolAddress((void**)&ah, g_ah);
    cudaGetSymbolAddress((void**)&al, g_al);
    cudaGetSymbolAddress((void**)&wh, g_wh);
    cudaGetSymbolAddress((void**)&wl, g_wl);
    cudaGetSymbolAddress((void**)&hA, g_hA);
    cudaGetSymbolAddress((void**)&hB, g_hB);
    cudaGetSymbolAddress((void**)&cb, g_c);
    cudaGetSymbolAddress((void**)&h0f, g_h0f);
    cudaGetSymbolAddress((void**)&c0f, g_c0f);
    cudaGetSymbolAddress((void**)&h1f, g_h1f);
    cudaGetSymbolAddress((void**)&c1f, g_c1f);

    const int NST = Bb * Hh;

    // launch #1: reset the (monotonic) grid-barrier counter once per invocation
    zero_bar_kernel<<<1, 1>>>();

    // ================= ENCODER layer 0 =================
    {
        int total = Ss * Bb * (Ee / 2);  // launch #2
        gather_split_kernel<<<(total + 255) / 256, 256>>>(src, enc_emb, ah, al, Ss);
    }
    split_w(enc_Wih0, wh, wl, G4 * Ee);                       // #3
    gemm_tc(ah, al, wh, wl, enc_b0, pre, Bb * Ss, G4, Ee, 0); // #4
    zero2_kernel<<<(NST + 255) / 256, 256>>>(hA, cb, NST);    // #5
    // launch #6 — profiled by ncu (-s 5 -c 1)
    run_lstm_layer(pre, enc_Whh0, hA, cb, hA, hB, seq, c0f, Ss, 0);
    copy_kernel<<<(NST + 255) / 256, 256>>>(h0f, hA, NST);

    // ================= ENCODER layer 1 (only final state needed) =================
    split_w(seq, ah, al, Bb * Ss * Hh);
    split_w(enc_Wih1, wh, wl, G4 * Hh);
    gemm_tc(ah, al, wh, wl, enc_b1, pre, Bb * Ss, G4, Hh, 0);
    zero2_kernel<<<(NST + 255) / 256, 256>>>(hA, cb, NST);
    run_lstm_layer(pre, enc_Whh1, hA, cb, hA, hB, (float*)0, c1f, Ss, 128 * 128);
    copy_kernel<<<(NST + 255) / 256, 256>>>(h1f, hA, NST);

    // ================= DECODER layer 0 (T = 127) =================
    const int Td = Ss - 1;
    {
        int total = Td * Bb * (Ee / 2);
        gather_split_kernel<<<(total + 255) / 256, 256>>>(trg, dec_emb, ah, al, Td);
    }
    split_w(dec_Wih0, wh, wl, G4 * Ee);
    gemm_tc(ah, al, wh, wl, dec_b0, pre, Bb * Td, G4, Ee, 0);
    run_lstm_layer(pre, dec_Whh0, h0f, c0f, hA, hB, seq, (float*)0, Td, 256 * 128);

    // ================= DECODER layer 1 =================
    split_w(seq, ah, al, Bb * Td * Hh);
    split_w(dec_Wih1, wh, wl, G4 * Hh);
    gemm_tc(ah, al, wh, wl, dec_b1, pre, Bb * Td, G4, Hh, 0);
    run_lstm_layer(pre, dec_Whh1, h1f, c1f, hA, hB, seq, (float*)0, Td, 383 * 128);

    // ================= Classifier =================
    split_w(seq, ah, al, Bb * Td * Hh);
    split_w(fc_W, wh, wl, Vv * Hh);
    zero_t0_kernel<<<(Bb * Vv + 255) / 256, 256>>>(out);
    gemm_tc(ah, al, wh, wl, fc_b, out, Bb * Td, Vv, Hh, 1);
}

// round 14
// speedup vs baseline: 1.5519x; 1.5395x over previous
#include <cuda_runtime.h>
#include <cuda_bf16.h>
#include <math.h>
#include <stdint.h>

// Problem constants
#define Bb 16
#define Ss 128
#define Ee 512
#define Hh 1024
#define G4 4096
#define Vv 32000

// ---------------- static scratch (no allocations allowed) ----------------
__device__ float g_pre[2048 * 4096];         // precomputed input gates + bias [T*B, 4H]
__device__ __nv_bfloat16 g_ah[2048 * 1024];  // A operand hi / h-history hi
__device__ __nv_bfloat16 g_al[2048 * 1024];  // A operand lo / h-history lo
__device__ __nv_bfloat16 g_wh[32000 * 1024]; // W operand hi (reused per GEMM)
__device__ __nv_bfloat16 g_wl[32000 * 1024]; // W operand lo
__device__ float g_hA[16 * 1024];            // zero h_init
__device__ float g_c[16 * 1024];             // zero c_init
__device__ float g_h0f[16 * 1024];
__device__ float g_c0f[16 * 1024];
__device__ float g_h1f[16 * 1024];
__device__ float g_c1f[16 * 1024];
__device__ unsigned g_bar;

// ---------------- PTX helpers ----------------
__device__ __forceinline__ uint32_t smem_u32(const void* p) {
    uint32_t a;
    asm("{ .reg .u64 t; cvta.to.shared.u64 t, %1; cvt.u32.u64 %0, t; }" : "=r"(a) : "l"(p));
    return a;
}

__device__ __forceinline__ void cp16(uint32_t dst, const void* src, int sz) {
    asm volatile("cp.async.cg.shared.global [%0], [%1], 16, %2;"
                 :: "r"(dst), "l"(src), "r"(sz) : "memory");
}

#define LDSM4(r0, r1, r2, r3, addr) \
    asm volatile("ldmatrix.sync.aligned.m8n8.x4.shared.b16 {%0,%1,%2,%3}, [%4];" \
                 : "=r"(r0), "=r"(r1), "=r"(r2), "=r"(r3) : "r"(addr))

#define MMA16816(c, a0, a1, a2, a3, b0, b1) \
    asm volatile("mma.sync.aligned.m16n8k16.row.col.f32.bf16.bf16.f32 " \
                 "{%0,%1,%2,%3}, {%4,%5,%6,%7}, {%8,%9}, {%0,%1,%2,%3};" \
                 : "+f"((c)[0]), "+f"((c)[1]), "+f"((c)[2]), "+f"((c)[3]) \
                 : "r"(a0), "r"(a1), "r"(a2), "r"(a3), "r"(b0), "r"(b1))

// ---------------- tiny utility kernels ----------------
__global__ void zero_bar_kernel() { g_bar = 0u; }

__global__ void zero2_kernel(float* __restrict__ a, float* __restrict__ b, int n) {
    int i = blockIdx.x * blockDim.x + threadIdx.x;
    if (i < n) { a[i] = 0.0f; b[i] = 0.0f; }
}

__global__ void zero_t0_kernel(float* __restrict__ out) {
    int i = blockIdx.x * blockDim.x + threadIdx.x;
    if (i < Bb * Vv) {
        int m = i / Vv;
        int n = i - m * Vv;
        out[(size_t)m * Ss * Vv + n] = 0.0f;
    }
}

// split fp32 -> bf16 hi + bf16 lo (vec4) — weights
__global__ void split4_kernel(const float* __restrict__ in, __nv_bfloat16* __restrict__ hi,
                              __nv_bfloat16* __restrict__ lo, int n4) {
    int i = blockIdx.x * blockDim.x + threadIdx.x;
    if (i >= n4) return;
    float4 v = ((const float4*)in)[i];
    __nv_bfloat16 h0 = __float2bfloat16(v.x);
    __nv_bfloat16 h1 = __float2bfloat16(v.y);
    __nv_bfloat16 h2 = __float2bfloat16(v.z);
    __nv_bfloat16 h3 = __float2bfloat16(v.w);
    __nv_bfloat162* H = (__nv_bfloat162*)hi;
    __nv_bfloat162* L = (__nv_bfloat162*)lo;
    H[2 * i + 0] = __nv_bfloat162(h0, h1);
    H[2 * i + 1] = __nv_bfloat162(h2, h3);
    L[2 * i + 0] = __nv_bfloat162(__float2bfloat16(v.x - __bfloat162float(h0)),
                                  __float2bfloat16(v.y - __bfloat162float(h1)));
    L[2 * i + 1] = __nv_bfloat162(__float2bfloat16(v.z - __bfloat162float(h2)),
                                  __float2bfloat16(v.w - __bfloat162float(h3)));
}

// Embedding gather + bf16 split: out rows [(t*B+m), E]
__global__ void gather_split_kernel(const int* __restrict__ tok, const float* __restrict__ emb,
                                    __nv_bfloat16* __restrict__ hi, __nv_bfloat16* __restrict__ lo,
                                    int T) {
    int idx = blockIdx.x * blockDim.x + threadIdx.x;  // float2 index
    int total = T * Bb * (Ee / 2);
    if (idx >= total) return;
    int e2 = idx & (Ee / 2 - 1);
    int r = idx >> 8;
    int m = r & (Bb - 1);
    int t = r >> 4;
    int token = tok[m * Ss + t];
    float2 v = *(const float2*)(emb + (size_t)token * Ee + e2 * 2);
    __nv_bfloat16 h0 = __float2bfloat16(v.x);
    __nv_bfloat16 h1 = __float2bfloat16(v.y);
    ((__nv_bfloat162*)hi)[(size_t)r * (Ee / 2) + e2] = __nv_bfloat162(h0, h1);
    ((__nv_bfloat162*)lo)[(size_t)r * (Ee / 2) + e2] =
        __nv_bfloat162(__float2bfloat16(v.x - __bfloat162float(h0)),
                       __float2bfloat16(v.y - __bfloat162float(h1)));
}

// ---------------- mma.sync split-bf16 GEMM (8 warps, 2-stage, 2 CTAs/SM) -------
#define RSB 80
#define TILE_BYTES (128 * RSB)        // 10240
#define STAGE_BYTES (4 * TILE_BYTES)  // 40960 (Ah, Al, Bh, Bl)
#define NSTAGE 2
#define GEMM_SMEM (NSTAGE * STAGE_BYTES)  // 81920 -> 2 CTAs/SM

__device__ __forceinline__ void load_stage_mma(
    uint32_t base, const __nv_bfloat16* __restrict__ Ah, const __nv_bfloat16* __restrict__ Al,
    const __nv_bfloat16* __restrict__ Bh, const __nv_bfloat16* __restrict__ Bl,
    int m0, int n0, int M, int K, int kc, int tid) {
    int k0 = kc * 32;
#pragma unroll
    for (int i = 0; i < 2; i++) {
        int chunk = tid + (i << 8);   // 0..511
        int row = chunk >> 2;         // 0..127
        int c4 = chunk & 3;           // 16B chunk within 64B row
        uint32_t smoff = row * RSB + c4 * 16;
        int gk = k0 + c4 * 8;
        int gm = m0 + row;
        int oka = (gm < M);
        size_t aoff = (size_t)(oka ? gm : 0) * K + gk;
        cp16(base + smoff, Ah + aoff, oka ? 16 : 0);
        cp16(base + TILE_BYTES + smoff, Al + aoff, oka ? 16 : 0);
        size_t boff = (size_t)(n0 + row) * K + gk;
        cp16(base + 2 * TILE_BYTES + smoff, Bh + boff, 16);
        cp16(base + 3 * TILE_BYTES + smoff, Bl + boff, 16);
    }
}

__global__ __launch_bounds__(256, 2) void gemm_mma_kernel(
    const __nv_bfloat16* __restrict__ Ah, const __nv_bfloat16* __restrict__ Al,
    const __nv_bfloat16* __restrict__ Bh, const __nv_bfloat16* __restrict__ Bl,
    const float* __restrict__ bias, float* __restrict__ C,
    int M, int N, int K, int mode) {
    extern __shared__ char smem[];
    uint32_t sb = smem_u32(smem);
    int tid = threadIdx.x;
    int lane = tid & 31;
    int warp = tid >> 5;
    int wm = (warp >> 2) * 64;
    int wn = (warp & 3) * 32;
    int m0 = blockIdx.y * 128;
    int n0 = blockIdx.x * 128;

    float acc[4][4][4];
#pragma unroll
    for (int i = 0; i < 4; i++)
#pragma unroll
        for (int j = 0; j < 4; j++)
#pragma unroll
            for (int q = 0; q < 4; q++) acc[i][j][q] = 0.0f;

    const int NC = K >> 5;

    load_stage_mma(sb, Ah, Al, Bh, Bl, m0, n0, M, K, 0, tid);
    asm volatile("cp.async.commit_group;" ::: "memory");

    uint32_t a_row = wm + (lane & 15);
    uint32_t a_kb = (lane >> 4) * 16;
    uint32_t b_row = wn + (lane & 7) + ((lane >> 4) << 3);
    uint32_t b_kb = ((lane >> 3) & 1) * 16;

    int slot = 0;
    int lslot = 1;

    for (int kc = 0; kc < NC; kc++) {
        asm volatile("cp.async.wait_group 0;" ::: "memory");
        __syncthreads();
        if (kc + 1 < NC) {
            load_stage_mma(sb + lslot * STAGE_BYTES, Ah, Al, Bh, Bl, m0, n0, M, K,
                           kc + 1, tid);
        }
        asm volatile("cp.async.commit_group;" ::: "memory");

        uint32_t stage = sb + slot * STAGE_BYTES;
#pragma unroll
        for (int kk = 0; kk < 2; kk++) {
            uint32_t kbyte = kk * 32;
            uint32_t ah[4][4], al[4][4];
#pragma unroll
            for (int mi = 0; mi < 4; mi++) {
                uint32_t ad = stage + (a_row + mi * 16) * RSB + kbyte + a_kb;
                LDSM4(ah[mi][0], ah[mi][1], ah[mi][2], ah[mi][3], ad);
            }
#pragma unroll
            for (int mi = 0; mi < 4; mi++) {
                uint32_t ad = stage + TILE_BYTES + (a_row + mi * 16) * RSB + kbyte + a_kb;
                LDSM4(al[mi][0], al[mi][1], al[mi][2], al[mi][3], ad);
            }
#pragma unroll
            for (int ni = 0; ni < 2; ni++) {
                uint32_t b0, b1, b2, b3;
                uint32_t bd = stage + 2 * TILE_BYTES + (b_row + ni * 16) * RSB + kbyte + b_kb;
                LDSM4(b0, b1, b2, b3, bd);  // Bh n16
#pragma unroll
                for (int mi = 0; mi < 4; mi++) {
                    MMA16816(acc[mi][ni * 2], ah[mi][0], ah[mi][1], ah[mi][2], ah[mi][3], b0, b1);
                    MMA16816(acc[mi][ni * 2 + 1], ah[mi][0], ah[mi][1], ah[mi][2], ah[mi][3], b2, b3);
                }
#pragma unroll
                for (int mi = 0; mi < 4; mi++) {
                    MMA16816(acc[mi][ni * 2], al[mi][0], al[mi][1], al[mi][2], al[mi][3], b0, b1);
                    MMA16816(acc[mi][ni * 2 + 1], al[mi][0], al[mi][1], al[mi][2], al[mi][3], b2, b3);
                }
                uint32_t ld = stage + 3 * TILE_BYTES + (b_row + ni * 16) * RSB + kbyte + b_kb;
                LDSM4(b0, b1, b2, b3, ld);  // Bl n16
#pragma unroll
                for (int mi = 0; mi < 4; mi++) {
                    MMA16816(acc[mi][ni * 2], ah[mi][0], ah[mi][1], ah[mi][2], ah[mi][3], b0, b1);
                    MMA16816(acc[mi][ni * 2 + 1], ah[mi][0], ah[mi][1], ah[mi][2], ah[mi][3], b2, b3);
                }
            }
        }
        slot ^= 1;
        lslot ^= 1;
    }

    int rbase = m0 + wm + (lane >> 2);
    int cbase = n0 + wn + 2 * (lane & 3);
#pragma unroll
    for (int mi = 0; mi < 4; mi++) {
#pragma unroll
        for (int half = 0; half < 2; half++) {
            int m = rbase + mi * 16 + half * 8;
            if (m >= M) continue;
            int orow = mode ? ((m & (Bb - 1)) * Ss + (m >> 4) + 1) : m;
            float* crow = C + (size_t)orow * N;
#pragma unroll
            for (int nj = 0; nj < 4; nj++) {
                int n = cbase + nj * 8;
                float2 v;
                v.x = acc[mi][nj][half * 2 + 0] + bias[n];
                v.y = acc[mi][nj][half * 2 + 1] + bias[n + 1];
                *(float2*)(crow + n) = v;
            }
        }
    }
}

// ---------------- persistent LSTM layer kernel (tensor-core recurrence) --------
// 128 CTAs x 256 threads; CTA owns 8 hidden units (32 Whh rows). Whh converted
// once to bf16 hi/lo smem. h history lives in yh/yl (bf16 hi/lo, seq layout,
// written at activation time); per-step gates via m16n8k16 split-bf16 HMMA.
// smem rows: stride 2064 B (1032 bf16) -> conflict-free ldmatrix.
#define WHROW 2064
#define L_WHI 0
#define L_WLO 66048
#define L_HHI 132096
#define L_HLO 165120
#define L_RED 198144
#define L_CS 214528
#define LSTM_SMEM 215040

__global__ __launch_bounds__(256) void lstm_layer_kernel(
    const float* __restrict__ pre, const float* __restrict__ Whh,
    const float* __restrict__ h_init, const float* __restrict__ c_init,
    __nv_bfloat16* __restrict__ yh, __nv_bfloat16* __restrict__ yl,
    float* __restrict__ h_fin, float* __restrict__ c_fin,
    int T, unsigned bar_base) {
    extern __shared__ char smc[];
    float* red = (float*)(smc + L_RED);  // [8 warps][4 tiles][32 lanes][4]
    float* cs = (float*)(smc + L_CS);    // 128

    int tid = threadIdx.x;
    int lane = tid & 31;
    int warp = tid >> 5;
    int j0 = blockIdx.x * 8;

    // Convert Whh slice to bf16 hi/lo smem (once per layer)
    for (int idx = tid; idx < 32 * 256; idx += 256) {
        int r = idx >> 8, c4 = idx & 255;
        int g = r >> 3, jj = r & 7;
        float4 v = *(const float4*)(Whh + (size_t)(g * Hh + j0 + jj) * Hh + c4 * 4);
        __nv_bfloat16 b0 = __float2bfloat16(v.x), b1 = __float2bfloat16(v.y);
        __nv_bfloat16 b2 = __float2bfloat16(v.z), b3 = __float2bfloat16(v.w);
        char* ph = smc + L_WHI + r * WHROW + c4 * 8;
        *(__nv_bfloat162*)ph = __nv_bfloat162(b0, b1);
        *(__nv_bfloat162*)(ph + 4) = __nv_bfloat162(b2, b3);
        char* pl = smc + L_WLO + r * WHROW + c4 * 8;
        *(__nv_bfloat162*)pl =
            __nv_bfloat162(__float2bfloat16(v.x - __bfloat162float(b0)),
                           __float2bfloat16(v.y - __bfloat162float(b1)));
        *(__nv_bfloat162*)(pl + 4) =
            __nv_bfloat162(__float2bfloat16(v.z - __bfloat162float(b2)),
                           __float2bfloat16(v.w - __bfloat162float(b3)));
    }
    if (tid < 128) cs[tid] = c_init[(tid & 15) * Hh + j0 + (tid >> 4)];
    __syncthreads();

    // per-lane ldmatrix address bases (same mapping as GEMM kernel)
    uint32_t aHi = smem_u32(smc + L_HHI) + (lane & 15) * WHROW + ((lane >> 4) << 4) +
                   warp * 256;
    uint32_t aLo = aHi + (L_HLO - L_HHI);
    uint32_t bHi = smem_u32(smc + L_WHI) +
                   ((lane & 7) + ((lane >> 4) << 3)) * WHROW + (((lane >> 3) & 1) << 4) +
                   warp * 256;
    uint32_t bLo = bHi + (L_WLO - L_WHI);

    for (int s = 0; s < T; s++) {
        // prefetch this step's pre gate values (consumed after reduction)
        float p0 = 0.f, p1 = 0.f, p2 = 0.f, p3 = 0.f;
        if (tid < 128) {
            int m = tid & 15, jr = tid >> 4;
            const float* pm = pre + (size_t)(s * Bb + m) * G4 + j0 + jr;
            p0 = __ldcg(pm);
            p1 = __ldcg(pm + Hh);
            p2 = __ldcg(pm + 2 * Hh);
            p3 = __ldcg(pm + 3 * Hh);
        }

        // stage h (bf16 hi/lo) into smem
        if (s == 0) {
            for (int idx = tid; idx < 4096; idx += 256) {  // 16 x 256 float4
                int m = idx >> 8, c4 = idx & 255;
                float4 v = *(const float4*)(h_init + (size_t)m * Hh + c4 * 4);
                __nv_bfloat16 b0 = __float2bfloat16(v.x), b1 = __float2bfloat16(v.y);
                __nv_bfloat16 b2 = __float2bfloat16(v.z), b3 = __float2bfloat16(v.w);
                char* ph = smc + L_HHI + m * WHROW + c4 * 8;
                *(__nv_bfloat162*)ph = __nv_bfloat162(b0, b1);
                *(__nv_bfloat162*)(ph + 4) = __nv_bfloat162(b2, b3);
                char* pl = smc + L_HLO + m * WHROW + c4 * 8;
                *(__nv_bfloat162*)pl =
                    __nv_bfloat162(__float2bfloat16(v.x - __bfloat162float(b0)),
                                   __float2bfloat16(v.y - __bfloat162float(b1)));
                *(__nv_bfloat162*)(pl + 4) =
                    __nv_bfloat162(__float2bfloat16(v.z - __bfloat162float(b2)),
                                   __float2bfloat16(v.w - __bfloat162float(b3)));
            }
        } else {
            const uint4* srcH = (const uint4*)(yh + (size_t)(s - 1) * Bb * Hh);
            const uint4* srcL = (const uint4*)(yl + (size_t)(s - 1) * Bb * Hh);
#pragma unroll
            for (int it = 0; it < 8; it++) {
                int chunk = tid + (it << 8);  // 0..2047
                int m = chunk >> 7, c16 = chunk & 127;  // 128 uint4 per 1024-bf16 row
                uint4 v = __ldcg(srcH + (size_t)m * 128 + c16);
                *(uint4*)(smc + L_HHI + m * WHROW + c16 * 16) = v;
                uint4 w = __ldcg(srcL + (size_t)m * 128 + c16);
                *(uint4*)(smc + L_HLO + m * WHROW + c16 * 16) = w;
            }
        }
        __syncthreads();

        float acc[4][4];
#pragma unroll
        for (int t = 0; t < 4; t++)
#pragma unroll
            for (int q = 0; q < 4; q++) acc[t][q] = 0.0f;

#pragma unroll
        for (int kw = 0; kw < 8; kw++) {
            uint32_t ko = kw * 32;
            uint32_t a0, a1, a2, a3, l0, l1, l2, l3;
            LDSM4(a0, a1, a2, a3, aHi + ko);
            LDSM4(l0, l1, l2, l3, aLo + ko);
#pragma unroll
            for (int n2 = 0; n2 < 2; n2++) {
                uint32_t off = (uint32_t)n2 * (16 * WHROW) + ko;
                uint32_t b0, b1, b2, b3;
                LDSM4(b0, b1, b2, b3, bHi + off);
                MMA16816(acc[n2 * 2], a0, a1, a2, a3, b0, b1);
                MMA16816(acc[n2 * 2 + 1], a0, a1, a2, a3, b2, b3);
                MMA16816(acc[n2 * 2], l0, l1, l2, l3, b0, b1);
                MMA16816(acc[n2 * 2 + 1], l0, l1, l2, l3, b2, b3);
                LDSM4(b0, b1, b2, b3, bLo + off);
                MMA16816(acc[n2 * 2], a0, a1, a2, a3, b0, b1);
                MMA16816(acc[n2 * 2 + 1], a0, a1, a2, a3, b2, b3);
            }
        }
        // store raw fragments (conflict-free st.128)
#pragma unroll
        for (int t = 0; t < 4; t++) {
            *(float4*)(red + ((size_t)(warp * 4 + t) * 32 + lane) * 4) =
                make_float4(acc[t][0], acc[t][1], acc[t][2], acc[t][3]);
        }
        __syncthreads();

        if (tid < 128) {
            int m = tid & 15, jr = tid >> 4;
            int lsrc = ((m & 7) << 2) + ((jr >> 1) & 3);
            int c = ((m >> 3) << 1) + (jr & 1);
            float gate[4];
#pragma unroll
            for (int g = 0; g < 4; g++) {
                float sum = 0.0f;
#pragma unroll
                for (int w = 0; w < 8; w++)
                    sum += red[((w * 4 + g) * 32 + lsrc) * 4 + c];
                gate[g] = sum;
            }
            float pi = p0 + gate[0];
            float pf = p1 + gate[1];
            float pg = p2 + gate[2];
            float po = p3 + gate[3];
            float iv = 1.0f / (1.0f + expf(-pi));
            float fv = 1.0f / (1.0f + expf(-pf));
            float gv = tanhf(pg);
            float ov = 1.0f / (1.0f + expf(-po));
            float cn = fv * cs[tid] + iv * gv;
            float hn = ov * tanhf(cn);
            cs[tid] = cn;
            int col = j0 + jr;
            __nv_bfloat16 hh = __float2bfloat16(hn);
            __nv_bfloat16 hl = __float2bfloat16(hn - __bfloat162float(hh));
            size_t o = (size_t)(s * Bb + m) * Hh + col;
            yh[o] = hh;
            yl[o] = hl;
            if (h_fin && s == T - 1) h_fin[m * Hh + col] = hn;
        }
        __threadfence();
        __syncthreads();
        if (tid == 0) {
            atomicAdd(&g_bar, 1u);
            unsigned target = bar_base + (unsigned)(s + 1) * 128u;
            while (*(volatile unsigned*)&g_bar < target) {}
            __threadfence();
        }
        __syncthreads();
    }

    if (c_fin && tid < 128) {
        c_fin[(tid & 15) * Hh + j0 + (tid >> 4)] = cs[tid];
    }
}

// ---------------- host orchestration ----------------
static inline void split_w(const float* w, __nv_bfloat16* hi, __nv_bfloat16* lo, int n) {
    int n4 = n / 4;
    split4_kernel<<<(n4 + 255) / 256, 256>>>(w, hi, lo, n4);
}

static inline void gemm_tc(const __nv_bfloat16* Ah, const __nv_bfloat16* Al,
                           const __nv_bfloat16* Bh, const __nv_bfloat16* Bl,
                           const float* bias, float* C, int M, int N, int K, int mode) {
    dim3 grid(N / 128, (M + 127) / 128);
    gemm_mma_kernel<<<grid, 256, GEMM_SMEM>>>(Ah, Al, Bh, Bl, bias, C, M, N, K, mode);
}

extern "C" void kernel_launch(void* const* d_in, const int* in_sizes, int n_in,
                              void* d_out, int out_size) {
    const int* src = (const int*)d_in[0];
    const int* trg = (const int*)d_in[1];
    const float* enc_emb = (const float*)d_in[2];
    const float* dec_emb = (const float*)d_in[3];
    const float* enc_Wih0 = (const float*)d_in[4];
    const float* enc_Whh0 = (const float*)d_in[5];
    const float* enc_b0 = (const float*)d_in[6];
    const float* enc_Wih1 = (const float*)d_in[7];
    const float* enc_Whh1 = (const float*)d_in[8];
    const float* enc_b1 = (const float*)d_in[9];
    const float* dec_Wih0 = (const float*)d_in[10];
    const float* dec_Whh0 = (const float*)d_in[11];
    const float* dec_b0 = (const float*)d_in[12];
    const float* dec_Wih1 = (const float*)d_in[13];
    const float* dec_Whh1 = (const float*)d_in[14];
    const float* dec_b1 = (const float*)d_in[15];
    const float* fc_W = (const float*)d_in[16];
    const float* fc_b = (const float*)d_in[17];
    float* out = (float*)d_out;

    cudaFuncSetAttribute(gemm_mma_kernel, cudaFuncAttributeMaxDynamicSharedMemorySize,
                         GEMM_SMEM);
    cudaFuncSetAttribute(lstm_layer_kernel, cudaFuncAttributeMaxDynamicSharedMemorySize,
                         LSTM_SMEM);

    float *pre, *hA, *cb, *h0f, *c0f, *h1f, *c1f;
    __nv_bfloat16 *ah, *al, *wh, *wl;
    cudaGetSymbolAddress((void**)&pre, g_pre);
    cudaGetSymbolAddress((void**)&ah, g_ah);
    cudaGetSymbolAddress((void**)&al, g_al);
    cudaGetSymbolAddress((void**)&wh, g_wh);
    cudaGetSymbolAddress((void**)&wl, g_wl);
    cudaGetSymbolAddress((void**)&hA, g_hA);
    cudaGetSymbolAddress((void**)&cb, g_c);
    cudaGetSymbolAddress((void**)&h0f, g_h0f);
    cudaGetSymbolAddress((void**)&c0f, g_c0f);
    cudaGetSymbolAddress((void**)&h1f, g_h1f);
    cudaGetSymbolAddress((void**)&c1f, g_c1f);

    const int NST = Bb * Hh;
    const int Td = Ss - 1;

    zero_bar_kernel<<<1, 1>>>();
    zero2_kernel<<<(NST + 255) / 256, 256>>>(hA, cb, NST);  // zero h_init / c_init

    // ================= ENCODER layer 0 =================
    {
        int total = Ss * Bb * (Ee / 2);
        gather_split_kernel<<<(total + 255) / 256, 256>>>(src, enc_emb, ah, al, Ss);
    }
    split_w(enc_Wih0, wh, wl, G4 * Ee);
    gemm_tc(ah, al, wh, wl, enc_b0, pre, Bb * Ss, G4, Ee, 0);
    lstm_layer_kernel<<<128, 256, LSTM_SMEM>>>(pre, enc_Whh0, hA, cb, ah, al, h0f, c0f,
                                               Ss, 0u);

    // ================= ENCODER layer 1 (final state only; y overwrites ah/al) ===
    split_w(enc_Wih1, wh, wl, G4 * Hh);
    gemm_tc(ah, al, wh, wl, enc_b1, pre, Bb * Ss, G4, Hh, 0);
    lstm_layer_kernel<<<128, 256, LSTM_SMEM>>>(pre, enc_Whh1, hA, cb, ah, al, h1f, c1f,
                                               Ss, 16384u);

    // ================= DECODER layer 0 (T = 127) =================
    {
        int total = Td * Bb * (Ee / 2);
        gather_split_kernel<<<(total + 255) / 256, 256>>>(trg, dec_emb, ah, al, Td);
    }
    split_w(dec_Wih0, wh, wl, G4 * Ee);
    gemm_tc(ah, al, wh, wl, dec_b0, pre, Bb * Td, G4, Ee, 0);
    lstm_layer_kernel<<<128, 256, LSTM_SMEM>>>(pre, dec_Whh0, h0f, c0f, ah, al,
                                               (float*)0, (float*)0, Td, 32768u);

    // ================= DECODER layer 1 =================
    split_w(dec_Wih1, wh, wl, G4 * Hh);
    gemm_tc(ah, al, wh, wl, dec_b1, pre, Bb * Td, G4, Hh, 0);
    lstm_layer_kernel<<<128, 256, LSTM_SMEM>>>(pre, dec_Whh1, h1f, c1f, ah, al,
                                               (float*)0, (float*)0, Td, 49024u);

    // ================= Classifier (dec1 y already split in ah/al) =================
    split_w(fc_W, wh, wl, Vv * Hh);
    zero_t0_kernel<<<(Bb * Vv + 255) / 256, 256>>>(out);
    gemm_tc(ah, al, wh, wl, fc_b, out, Bb * Td, Vv, Hh, 1);
}

// round 17
// speedup vs baseline: 1.6959x; 1.0928x over previous
#include <cuda_runtime.h>
#include <cuda_bf16.h>
#include <math.h>
#include <stdint.h>

// Problem constants
#define Bb 16
#define Ss 128
#define Ee 512
#define Hh 1024
#define G4 4096
#define Vv 32000

// ---------------- static scratch (no allocations allowed) ----------------
__device__ float g_pre[2048 * 4096];         // precomputed input gates + bias [T*B, 4H]
__device__ __nv_bfloat16 g_ah[2048 * 1024];  // A operand hi / h-history hi
__device__ __nv_bfloat16 g_al[2048 * 1024];  // A operand lo / h-history lo
__device__ __nv_bfloat16 g_wh[32000 * 1024]; // W operand hi (reused per GEMM)
__device__ __nv_bfloat16 g_wl[32000 * 1024]; // W operand lo
__device__ float g_hA[16 * 1024];            // zero h_init
__device__ float g_c[16 * 1024];             // zero c_init
__device__ float g_h0f[16 * 1024];
__device__ float g_c0f[16 * 1024];
__device__ float g_h1f[16 * 1024];
__device__ float g_c1f[16 * 1024];
__device__ unsigned g_bar;

// ---------------- PTX helpers ----------------
__device__ __forceinline__ uint32_t smem_u32(const void* p) {
    uint32_t a;
    asm("{ .reg .u64 t; cvta.to.shared.u64 t, %1; cvt.u32.u64 %0, t; }" : "=r"(a) : "l"(p));
    return a;
}

__device__ __forceinline__ void cp16(uint32_t dst, const void* src, int sz) {
    asm volatile("cp.async.cg.shared.global [%0], [%1], 16, %2;"
                 :: "r"(dst), "l"(src), "r"(sz) : "memory");
}

#define LDSM4(r0, r1, r2, r3, addr) \
    asm volatile("ldmatrix.sync.aligned.m8n8.x4.shared.b16 {%0,%1,%2,%3}, [%4];" \
                 : "=r"(r0), "=r"(r1), "=r"(r2), "=r"(r3) : "r"(addr))

#define MMA16816(c, a0, a1, a2, a3, b0, b1) \
    asm volatile("mma.sync.aligned.m16n8k16.row.col.f32.bf16.bf16.f32 " \
                 "{%0,%1,%2,%3}, {%4,%5,%6,%7}, {%8,%9}, {%0,%1,%2,%3};" \
                 : "+f"((c)[0]), "+f"((c)[1]), "+f"((c)[2]), "+f"((c)[3]) \
                 : "r"(a0), "r"(a1), "r"(a2), "r"(a3), "r"(b0), "r"(b1))

// overflow-safe fast activations (MUFU-based, ~2 ulp)
__device__ __forceinline__ float fast_sig(float x) {
    return __fdividef(1.0f, 1.0f + __expf(-x));
}
__device__ __forceinline__ float fast_tanh(float x) {
    return 1.0f - __fdividef(2.0f, __expf(2.0f * x) + 1.0f);
}

// ---------------- tiny utility kernels ----------------
__global__ void zero_bar_kernel() { g_bar = 0u; }

__global__ void zero2_kernel(float* __restrict__ a, float* __restrict__ b, int n) {
    int i = blockIdx.x * blockDim.x + threadIdx.x;
    if (i < n) { a[i] = 0.0f; b[i] = 0.0f; }
}

__global__ void zero_t0_kernel(float* __restrict__ out) {
    int i = blockIdx.x * blockDim.x + threadIdx.x;
    if (i < Bb * Vv) {
        int m = i / Vv;
        int n = i - m * Vv;
        out[(size_t)m * Ss * Vv + n] = 0.0f;
    }
}

// split fp32 -> bf16 hi + bf16 lo; 4 independent float4 per thread (MLP=4)
__global__ void split4_kernel(const float* __restrict__ in, __nv_bfloat16* __restrict__ hi,
                              __nv_bfloat16* __restrict__ lo, int n4) {
    int base = blockIdx.x * 1024 + threadIdx.x;
    float4 v[4];
    int idx[4];
#pragma unroll
    for (int i = 0; i < 4; i++) {
        idx[i] = base + i * 256;
        if (idx[i] < n4) v[i] = ((const float4*)in)[idx[i]];
    }
    __nv_bfloat162* H = (__nv_bfloat162*)hi;
    __nv_bfloat162* L = (__nv_bfloat162*)lo;
#pragma unroll
    for (int i = 0; i < 4; i++) {
        if (idx[i] >= n4) continue;
        __nv_bfloat16 h0 = __float2bfloat16(v[i].x);
        __nv_bfloat16 h1 = __float2bfloat16(v[i].y);
        __nv_bfloat16 h2 = __float2bfloat16(v[i].z);
        __nv_bfloat16 h3 = __float2bfloat16(v[i].w);
        H[2 * idx[i] + 0] = __nv_bfloat162(h0, h1);
        H[2 * idx[i] + 1] = __nv_bfloat162(h2, h3);
        L[2 * idx[i] + 0] =
            __nv_bfloat162(__float2bfloat16(v[i].x - __bfloat162float(h0)),
                           __float2bfloat16(v[i].y - __bfloat162float(h1)));
        L[2 * idx[i] + 1] =
            __nv_bfloat162(__float2bfloat16(v[i].z - __bfloat162float(h2)),
                           __float2bfloat16(v[i].w - __bfloat162float(h3)));
    }
}

// Embedding gather + bf16 split: out rows [(t*B+m), E]
__global__ void gather_split_kernel(const int* __restrict__ tok, const float* __restrict__ emb,
                                    __nv_bfloat16* __restrict__ hi, __nv_bfloat16* __restrict__ lo,
                                    int T) {
    int idx = blockIdx.x * blockDim.x + threadIdx.x;  // float2 index
    int total = T * Bb * (Ee / 2);
    if (idx >= total) return;
    int e2 = idx & (Ee / 2 - 1);
    int r = idx >> 8;
    int m = r & (Bb - 1);
    int t = r >> 4;
    int token = tok[m * Ss + t];
    float2 v = *(const float2*)(emb + (size_t)token * Ee + e2 * 2);
    __nv_bfloat16 h0 = __float2bfloat16(v.x);
    __nv_bfloat16 h1 = __float2bfloat16(v.y);
    ((__nv_bfloat162*)hi)[(size_t)r * (Ee / 2) + e2] = __nv_bfloat162(h0, h1);
    ((__nv_bfloat162*)lo)[(size_t)r * (Ee / 2) + e2] =
        __nv_bfloat162(__float2bfloat16(v.x - __bfloat162float(h0)),
                       __float2bfloat16(v.y - __bfloat162float(h1)));
}

// ---------------- mma.sync split-bf16 GEMM (8 warps, 2-stage, 2 CTAs/SM) -------
#define RSB 80
#define TILE_BYTES (128 * RSB)        // 10240
#define STAGE_BYTES (4 * TILE_BYTES)  // 40960 (Ah, Al, Bh, Bl)
#define NSTAGE 2
#define GEMM_SMEM (NSTAGE * STAGE_BYTES)  // 81920 -> 2 CTAs/SM

__device__ __forceinline__ void load_stage_mma(
    uint32_t base, const __nv_bfloat16* __restrict__ Ah, const __nv_bfloat16* __restrict__ Al,
    const __nv_bfloat16* __restrict__ Bh, const __nv_bfloat16* __restrict__ Bl,
    int m0, int n0, int M, int K, int kc, int tid) {
    int k0 = kc * 32;
#pragma unroll
    for (int i = 0; i < 2; i++) {
        int chunk = tid + (i << 8);   // 0..511
        int row = chunk >> 2;         // 0..127
        int c4 = chunk & 3;           // 16B chunk within 64B row
        uint32_t smoff = row * RSB + c4 * 16;
        int gk = k0 + c4 * 8;
        int gm = m0 + row;
        int oka = (gm < M);
        size_t aoff = (size_t)(oka ? gm : 0) * K + gk;
        cp16(base + smoff, Ah + aoff, oka ? 16 : 0);
        cp16(base + TILE_BYTES + smoff, Al + aoff, oka ? 16 : 0);
        size_t boff = (size_t)(n0 + row) * K + gk;
        cp16(base + 2 * TILE_BYTES + smoff, Bh + boff, 16);
        cp16(base + 3 * TILE_BYTES + smoff, Bl + boff, 16);
    }
}

__global__ __launch_bounds__(256, 2) void gemm_mma_kernel(
    const __nv_bfloat16* __restrict__ Ah, const __nv_bfloat16* __restrict__ Al,
    const __nv_bfloat16* __restrict__ Bh, const __nv_bfloat16* __restrict__ Bl,
    const float* __restrict__ bias, float* __restrict__ C,
    int M, int N, int K, int mode) {
    extern __shared__ char smem[];
    uint32_t sb = smem_u32(smem);
    int tid = threadIdx.x;
    int lane = tid & 31;
    int warp = tid >> 5;
    int wm = (warp >> 2) * 64;
    int wn = (warp & 3) * 32;
    int m0 = blockIdx.y * 128;
    int n0 = blockIdx.x * 128;

    float acc[4][4][4];
#pragma unroll
    for (int i = 0; i < 4; i++)
#pragma unroll
        for (int j = 0; j < 4; j++)
#pragma unroll
            for (int q = 0; q < 4; q++) acc[i][j][q] = 0.0f;

    const int NC = K >> 5;

    load_stage_mma(sb, Ah, Al, Bh, Bl, m0, n0, M, K, 0, tid);
    asm volatile("cp.async.commit_group;" ::: "memory");

    uint32_t a_row = wm + (lane & 15);
    uint32_t a_kb = (lane >> 4) * 16;
    uint32_t b_row = wn + (lane & 7) + ((lane >> 4) << 3);
    uint32_t b_kb = ((lane >> 3) & 1) * 16;

    int slot = 0;
    int lslot = 1;

    for (int kc = 0; kc < NC; kc++) {
        asm volatile("cp.async.wait_group 0;" ::: "memory");
        __syncthreads();
        if (kc + 1 < NC) {
            load_stage_mma(sb + lslot * STAGE_BYTES, Ah, Al, Bh, Bl, m0, n0, M, K,
                           kc + 1, tid);
        }
        asm volatile("cp.async.commit_group;" ::: "memory");

        uint32_t stage = sb + slot * STAGE_BYTES;
#pragma unroll
        for (int kk = 0; kk < 2; kk++) {
            uint32_t kbyte = kk * 32;
            uint32_t ah[4][4], al[4][4];
#pragma unroll
            for (int mi = 0; mi < 4; mi++) {
                uint32_t ad = stage + (a_row + mi * 16) * RSB + kbyte + a_kb;
                LDSM4(ah[mi][0], ah[mi][1], ah[mi][2], ah[mi][3], ad);
            }
#pragma unroll
            for (int mi = 0; mi < 4; mi++) {
                uint32_t ad = stage + TILE_BYTES + (a_row + mi * 16) * RSB + kbyte + a_kb;
                LDSM4(al[mi][0], al[mi][1], al[mi][2], al[mi][3], ad);
            }
#pragma unroll
            for (int ni = 0; ni < 2; ni++) {
                uint32_t b0, b1, b2, b3;
                uint32_t bd = stage + 2 * TILE_BYTES + (b_row + ni * 16) * RSB + kbyte + b_kb;
                LDSM4(b0, b1, b2, b3, bd);  // Bh n16
#pragma unroll
                for (int mi = 0; mi < 4; mi++) {
                    MMA16816(acc[mi][ni * 2], ah[mi][0], ah[mi][1], ah[mi][2], ah[mi][3], b0, b1);
                    MMA16816(acc[mi][ni * 2 + 1], ah[mi][0], ah[mi][1], ah[mi][2], ah[mi][3], b2, b3);
                }
#pragma unroll
                for (int mi = 0; mi < 4; mi++) {
                    MMA16816(acc[mi][ni * 2], al[mi][0], al[mi][1], al[mi][2], al[mi][3], b0, b1);
                    MMA16816(acc[mi][ni * 2 + 1], al[mi][0], al[mi][1], al[mi][2], al[mi][3], b2, b3);
                }
                uint32_t ld = stage + 3 * TILE_BYTES + (b_row + ni * 16) * RSB + kbyte + b_kb;
                LDSM4(b0, b1, b2, b3, ld);  // Bl n16
#pragma unroll
                for (int mi = 0; mi < 4; mi++) {
                    MMA16816(acc[mi][ni * 2], ah[mi][0], ah[mi][1], ah[mi][2], ah[mi][3], b0, b1);
                    MMA16816(acc[mi][ni * 2 + 1], ah[mi][0], ah[mi][1], ah[mi][2], ah[mi][3], b2, b3);
                }
            }
        }
        slot ^= 1;
        lslot ^= 1;
    }

    int rbase = m0 + wm + (lane >> 2);
    int cbase = n0 + wn + 2 * (lane & 3);
#pragma unroll
    for (int mi = 0; mi < 4; mi++) {
#pragma unroll
        for (int half = 0; half < 2; half++) {
            int m = rbase + mi * 16 + half * 8;
            if (m >= M) continue;
            int orow = mode ? ((m & (Bb - 1)) * Ss + (m >> 4) + 1) : m;
            float* crow = C + (size_t)orow * N;
#pragma unroll
            for (int nj = 0; nj < 4; nj++) {
                int n = cbase + nj * 8;
                float2 v;
                v.x = acc[mi][nj][half * 2 + 0] + bias[n];
                v.y = acc[mi][nj][half * 2 + 1] + bias[n + 1];
                *(float2*)(crow + n) = v;
            }
        }
    }
}

// ---------------- persistent LSTM layer kernel (tensor-core recurrence) --------
#define WHROW 2064
#define L_WHI 0
#define L_WLO 66048
#define L_HHI 132096
#define L_HLO 165120
#define L_RED 198144
#define L_CS 214528
#define LSTM_SMEM 215040

__global__ __launch_bounds__(256) void lstm_layer_kernel(
    const float* __restrict__ pre, const float* __restrict__ Whh,
    const float* __restrict__ h_init, const float* __restrict__ c_init,
    __nv_bfloat16* __restrict__ yh, __nv_bfloat16* __restrict__ yl,
    float* __restrict__ h_fin, float* __restrict__ c_fin,
    int T, unsigned bar_base) {
    extern __shared__ char smc[];
    float* red = (float*)(smc + L_RED);  // [8 warps][4 tiles][32 lanes][4]
    float* cs = (float*)(smc + L_CS);    // 128

    int tid = threadIdx.x;
    int lane = tid & 31;
    int warp = tid >> 5;
    int j0 = blockIdx.x * 8;

    // Convert Whh slice to bf16 hi/lo smem (once per layer)
    for (int idx = tid; idx < 32 * 256; idx += 256) {
        int r = idx >> 8, c4 = idx & 255;
        int g = r >> 3, jj = r & 7;
        float4 v = *(const float4*)(Whh + (size_t)(g * Hh + j0 + jj) * Hh + c4 * 4);
        __nv_bfloat16 b0 = __float2bfloat16(v.x), b1 = __float2bfloat16(v.y);
        __nv_bfloat16 b2 = __float2bfloat16(v.z), b3 = __float2bfloat16(v.w);
        char* ph = smc + L_WHI + r * WHROW + c4 * 8;
        *(__nv_bfloat162*)ph = __nv_bfloat162(b0, b1);
        *(__nv_bfloat162*)(ph + 4) = __nv_bfloat162(b2, b3);
        char* pl = smc + L_WLO + r * WHROW + c4 * 8;
        *(__nv_bfloat162*)pl =
            __nv_bfloat162(__float2bfloat16(v.x - __bfloat162float(b0)),
                           __float2bfloat16(v.y - __bfloat162float(b1)));
        *(__nv_bfloat162*)(pl + 4) =
            __nv_bfloat162(__float2bfloat16(v.z - __bfloat162float(b2)),
                           __float2bfloat16(v.w - __bfloat162float(b3)));
    }
    if (tid < 128) cs[tid] = c_init[(tid & 15) * Hh + j0 + (tid >> 4)];
    __syncthreads();

    uint32_t aHi = smem_u32(smc + L_HHI) + (lane & 15) * WHROW + ((lane >> 4) << 4) +
                   warp * 256;
    uint32_t aLo = aHi + (L_HLO - L_HHI);
    uint32_t bHi = smem_u32(smc + L_WHI) +
                   ((lane & 7) + ((lane >> 4) << 3)) * WHROW + (((lane >> 3) & 1) << 4) +
                   warp * 256;
    uint32_t bLo = bHi + (L_WLO - L_WHI);

    for (int s = 0; s < T; s++) {
        // prefetch this step's pre gate values (consumed after reduction)
        float p0 = 0.f, p1 = 0.f, p2 = 0.f, p3 = 0.f;
        if (tid < 128) {
            int m = tid & 15, jr = tid >> 4;
            const float* pm = pre + (size_t)(s * Bb + m) * G4 + j0 + jr;
            p0 = __ldcg(pm);
            p1 = __ldcg(pm + Hh);
            p2 = __ldcg(pm + 2 * Hh);
            p3 = __ldcg(pm + 3 * Hh);
        }

        // stage h (bf16 hi/lo) into smem
        if (s == 0) {
            for (int idx = tid; idx < 4096; idx += 256) {  // 16 x 256 float4
                int m = idx >> 8, c4 = idx & 255;
                float4 v = *(const float4*)(h_init + (size_t)m * Hh + c4 * 4);
                __nv_bfloat16 b0 = __float2bfloat16(v.x), b1 = __float2bfloat16(v.y);
                __nv_bfloat16 b2 = __float2bfloat16(v.z), b3 = __float2bfloat16(v.w);
                char* ph = smc + L_HHI + m * WHROW + c4 * 8;
                *(__nv_bfloat162*)ph = __nv_bfloat162(b0, b1);
                *(__nv_bfloat162*)(ph + 4) = __nv_bfloat162(b2, b3);
                char* pl = smc + L_HLO + m * WHROW + c4 * 8;
                *(__nv_bfloat162*)pl =
                    __nv_bfloat162(__float2bfloat16(v.x - __bfloat162float(b0)),
                                   __float2bfloat16(v.y - __bfloat162float(b1)));
                *(__nv_bfloat162*)(pl + 4) =
                    __nv_bfloat162(__float2bfloat16(v.z - __bfloat162float(b2)),
                                   __float2bfloat16(v.w - __bfloat162float(b3)));
            }
        } else {
            const uint4* srcH = (const uint4*)(yh + (size_t)(s - 1) * Bb * Hh);
            const uint4* srcL = (const uint4*)(yl + (size_t)(s - 1) * Bb * Hh);
#pragma unroll
            for (int it = 0; it < 8; it++) {
                int chunk = tid + (it << 8);  // 0..2047
                int m = chunk >> 7, c16 = chunk & 127;
                uint4 v = __ldcg(srcH + (size_t)m * 128 + c16);
                *(uint4*)(smc + L_HHI + m * WHROW + c16 * 16) = v;
                uint4 w = __ldcg(srcL + (size_t)m * 128 + c16);
                *(uint4*)(smc + L_HLO + m * WHROW + c16 * 16) = w;
            }
        }
        __syncthreads();

        float acc[4][4];
#pragma unroll
        for (int t = 0; t < 4; t++)
#pragma unroll
            for (int q = 0; q < 4; q++) acc[t][q] = 0.0f;

#pragma unroll
        for (int kw = 0; kw < 8; kw++) {
            uint32_t ko = kw * 32;
            uint32_t a0, a1, a2, a3, l0, l1, l2, l3;
            LDSM4(a0, a1, a2, a3, aHi + ko);
            LDSM4(l0, l1, l2, l3, aLo + ko);
#pragma unroll
            for (int n2 = 0; n2 < 2; n2++) {
                uint32_t off = (uint32_t)n2 * (16 * WHROW) + ko;
                uint32_t b0, b1, b2, b3;
                LDSM4(b0, b1, b2, b3, bHi + off);
                MMA16816(acc[n2 * 2], a0, a1, a2, a3, b0, b1);
                MMA16816(acc[n2 * 2 + 1], a0, a1, a2, a3, b2, b3);
                MMA16816(acc[n2 * 2], l0, l1, l2, l3, b0, b1);
                MMA16816(acc[n2 * 2 + 1], l0, l1, l2, l3, b2, b3);
                LDSM4(b0, b1, b2, b3, bLo + off);
                MMA16816(acc[n2 * 2], a0, a1, a2, a3, b0, b1);
                MMA16816(acc[n2 * 2 + 1], a0, a1, a2, a3, b2, b3);
            }
        }
#pragma unroll
        for (int t = 0; t < 4; t++) {
            *(float4*)(red + ((size_t)(warp * 4 + t) * 32 + lane) * 4) =
                make_float4(acc[t][0], acc[t][1], acc[t][2], acc[t][3]);
        }
        __syncthreads();

        if (tid < 128) {
            int m = tid & 15, jr = tid >> 4;
            int lsrc = ((m & 7) << 2) + ((jr >> 1) & 3);
            int c = ((m >> 3) << 1) + (jr & 1);
            float gate[4];
#pragma unroll
            for (int g = 0; g < 4; g++) {
                float sum = 0.0f;
#pragma unroll
                for (int w = 0; w < 8; w++)
                    sum += red[((w * 4 + g) * 32 + lsrc) * 4 + c];
                gate[g] = sum;
            }
            float pi = p0 + gate[0];
            float pf = p1 + gate[1];
            float pg = p2 + gate[2];
            float po = p3 + gate[3];
            float iv = fast_sig(pi);
            float fv = fast_sig(pf);
            float gv = fast_tanh(pg);
            float ov = fast_sig(po);
            float cn = fv * cs[tid] + iv * gv;
            float hn = ov * fast_tanh(cn);
            cs[tid] = cn;
            int col = j0 + jr;
            __nv_bfloat16 hh = __float2bfloat16(hn);
            __nv_bfloat16 hl = __float2bfloat16(hn - __bfloat162float(hh));
            size_t o = (size_t)(s * Bb + m) * Hh + col;
            yh[o] = hh;
            yl[o] = hl;
            if (h_fin && s == T - 1) h_fin[m * Hh + col] = hn;
        }
        __syncthreads();
        // lightweight grid barrier: tid0-only release/acquire (CG-style)
        if (tid == 0) {
            asm volatile("red.release.gpu.global.add.u32 [%0], %1;"
                         :: "l"(&g_bar), "r"(1u) : "memory");
            unsigned target = bar_base + (unsigned)(s + 1) * 128u;
            unsigned cur;
            do {
                asm volatile("ld.acquire.gpu.global.u32 %0, [%1];"
                             : "=r"(cur) : "l"(&g_bar) : "memory");
            } while ((int)(cur - target) < 0);
        }
        __syncthreads();
    }

    if (c_fin && tid < 128) {
        c_fin[(tid & 15) * Hh + j0 + (tid >> 4)] = cs[tid];
    }
}

// ---------------- host orchestration ----------------
static inline void split_w(const float* w, __nv_bfloat16* hi, __nv_bfloat16* lo, int n) {
    int n4 = n / 4;
    split4_kernel<<<(n4 + 1023) / 1024, 256>>>(w, hi, lo, n4);
}

static inline void gemm_tc(const __nv_bfloat16* Ah, const __nv_bfloat16* Al,
                           const __nv_bfloat16* Bh, const __nv_bfloat16* Bl,
                           const float* bias, float* C, int M, int N, int K, int mode) {
    dim3 grid(N / 128, (M + 127) / 128);
    gemm_mma_kernel<<<grid, 256, GEMM_SMEM>>>(Ah, Al, Bh, Bl, bias, C, M, N, K, mode);
}

extern "C" void kernel_launch(void* const* d_in, const int* in_sizes, int n_in,
                              void* d_out, int out_size) {
    const int* src = (const int*)d_in[0];
    const int* trg = (const int*)d_in[1];
    const float* enc_emb = (const float*)d_in[2];
    const float* dec_emb = (const float*)d_in[3];
    const float* enc_Wih0 = (const float*)d_in[4];
    const float* enc_Whh0 = (const float*)d_in[5];
    const float* enc_b0 = (const float*)d_in[6];
    const float* enc_Wih1 = (const float*)d_in[7];
    const float* enc_Whh1 = (const float*)d_in[8];
    const float* enc_b1 = (const float*)d_in[9];
    const float* dec_Wih0 = (const float*)d_in[10];
    const float* dec_Whh0 = (const float*)d_in[11];
    const float* dec_b0 = (const float*)d_in[12];
    const float* dec_Wih1 = (const float*)d_in[13];
    const float* dec_Whh1 = (const float*)d_in[14];
    const float* dec_b1 = (const float*)d_in[15];
    const float* fc_W = (const float*)d_in[16];
    const float* fc_b = (const float*)d_in[17];
    float* out = (float*)d_out;

    cudaFuncSetAttribute(gemm_mma_kernel, cudaFuncAttributeMaxDynamicSharedMemorySize,
                         GEMM_SMEM);
    cudaFuncSetAttribute(lstm_layer_kernel, cudaFuncAttributeMaxDynamicSharedMemorySize,
                         LSTM_SMEM);

    float *pre, *hA, *cb, *h0f, *c0f, *h1f, *c1f;
    __nv_bfloat16 *ah, *al, *wh, *wl;
    cudaGetSymbolAddress((void**)&pre, g_pre);
    cudaGetSymbolAddress((void**)&ah, g_ah);
    cudaGetSymbolAddress((void**)&al, g_al);
    cudaGetSymbolAddress((void**)&wh, g_wh);
    cudaGetSymbolAddress((void**)&wl, g_wl);
    cudaGetSymbolAddress((void**)&hA, g_hA);
    cudaGetSymbolAddress((void**)&cb, g_c);
    cudaGetSymbolAddress((void**)&h0f, g_h0f);
    cudaGetSymbolAddress((void**)&c0f, g_c0f);
    cudaGetSymbolAddress((void**)&h1f, g_h1f);
    cudaGetSymbolAddress((void**)&c1f, g_c1f);

    const int NST = Bb * Hh;
    const int Td = Ss - 1;

    zero_bar_kernel<<<1, 1>>>();
    zero2_kernel<<<(NST + 255) / 256, 256>>>(hA, cb, NST);  // zero h_init / c_init

    // ================= ENCODER layer 0 =================
    {
        int total = Ss * Bb * (Ee / 2);
        gather_split_kernel<<<(total + 255) / 256, 256>>>(src, enc_emb, ah, al, Ss);
    }
    split_w(enc_Wih0, wh, wl, G4 * Ee);
    gemm_tc(ah, al, wh, wl, enc_b0, pre, Bb * Ss, G4, Ee, 0);
    lstm_layer_kernel<<<128, 256, LSTM_SMEM>>>(pre, enc_Whh0, hA, cb, ah, al, h0f, c0f,
                                               Ss, 0u);

    // ================= ENCODER layer 1 (final state only; y overwrites ah/al) ===
    split_w(enc_Wih1, wh, wl, G4 * Hh);
    gemm_tc(ah, al, wh, wl, enc_b1, pre, Bb * Ss, G4, Hh, 0);
    lstm_layer_kernel<<<128, 256, LSTM_SMEM>>>(pre, enc_Whh1, hA, cb, ah, al, h1f, c1f,
                                               Ss, 16384u);

    // ================= DECODER layer 0 (T = 127) =================
    {
        int total = Td * Bb * (Ee / 2);
        gather_split_kernel<<<(total + 255) / 256, 256>>>(trg, dec_emb, ah, al, Td);
    }
    split_w(dec_Wih0, wh, wl, G4 * Ee);
    gemm_tc(ah, al, wh, wl, dec_b0, pre, Bb * Td, G4, Ee, 0);
    lstm_layer_kernel<<<128, 256, LSTM_SMEM>>>(pre, dec_Whh0, h0f, c0f, ah, al,
                                               (float*)0, (float*)0, Td, 32768u);

    // ================= DECODER layer 1 =================
    split_w(dec_Wih1, wh, wl, G4 * Hh);
    gemm_tc(ah, al, wh, wl, dec_b1, pre, Bb * Td, G4, Hh, 0);
    lstm_layer_kernel<<<128, 256, LSTM_SMEM>>>(pre, dec_Whh1, h1f, c1f, ah, al,
                                               (float*)0, (float*)0, Td, 49024u);

    // ================= Classifier (dec1 y already split in ah/al) =================
    split_w(fc_W, wh, wl, Vv * Hh);
    zero_t0_kernel<<<(Bb * Vv + 255) / 256, 256>>>(out);
    gemm_tc(ah, al, wh, wl, fc_b, out, Bb * Td, Vv, Hh, 1);
}